// round 1
// baseline (speedup 1.0000x reference)
#include <cuda_runtime.h>

#define TOKENS 4096
#define DMODEL 1024
#define NHEADS 16
#define SEQ 2048

// Scratch: Q,K,V in [B*H][S][64] layout; O in [token][dmodel] layout.
__device__ __align__(16) float g_Q[TOKENS * DMODEL];
__device__ __align__(16) float g_K[TOKENS * DMODEL];
__device__ __align__(16) float g_V[TOKENS * DMODEL];
__device__ __align__(16) float g_O[TOKENS * DMODEL];

__device__ __forceinline__ float neg_inf() { return __int_as_float(0xff800000u); }

// ---------------------------------------------------------------------------
// SGEMM core: C[m][n] = sum_k A[m][k] * B[n][k]   (both row-major, K inner)
// M=4096, N=1024, K=1024. 128x128 tile, KT=8, 256 threads, 8x8 micro-tile.
// ---------------------------------------------------------------------------

__global__ __launch_bounds__(256, 2) void sgemm_qkv_kernel(
    const float* __restrict__ x,
    const float* __restrict__ Wq,
    const float* __restrict__ Wk,
    const float* __restrict__ Wv)
{
    const float* B = (blockIdx.z == 0) ? Wq : (blockIdx.z == 1 ? Wk : Wv);
    float* C = (blockIdx.z == 0) ? g_Q : (blockIdx.z == 1 ? g_K : g_V);

    __shared__ __align__(16) float As[8][128];
    __shared__ __align__(16) float Bs[8][128];

    const int tid = threadIdx.x;
    const int m0 = blockIdx.y * 128;
    const int n0 = blockIdx.x * 128;
    const int lr = tid >> 1;
    const int lk = (tid & 1) << 2;
    const int ty = tid >> 4;   // 0..15 -> rows ty*8..+7
    const int tx = tid & 15;   // 0..15 -> cols tx*8..+7

    const float* ap = x + (m0 + lr) * DMODEL + lk;
    const float* bp = B + (n0 + lr) * DMODEL + lk;

    float acc[8][8];
#pragma unroll
    for (int i = 0; i < 8; i++)
#pragma unroll
        for (int j = 0; j < 8; j++) acc[i][j] = 0.f;

    for (int k0 = 0; k0 < DMODEL; k0 += 8) {
        float4 a = *(const float4*)(ap + k0);
        float4 b = *(const float4*)(bp + k0);
        __syncthreads();
        As[lk + 0][lr] = a.x; As[lk + 1][lr] = a.y;
        As[lk + 2][lr] = a.z; As[lk + 3][lr] = a.w;
        Bs[lk + 0][lr] = b.x; Bs[lk + 1][lr] = b.y;
        Bs[lk + 2][lr] = b.z; Bs[lk + 3][lr] = b.w;
        __syncthreads();
#pragma unroll
        for (int kk = 0; kk < 8; kk++) {
            float av[8], bv[8];
            *(float4*)(av)     = *(const float4*)(&As[kk][ty * 8]);
            *(float4*)(av + 4) = *(const float4*)(&As[kk][ty * 8 + 4]);
            *(float4*)(bv)     = *(const float4*)(&Bs[kk][tx * 8]);
            *(float4*)(bv + 4) = *(const float4*)(&Bs[kk][tx * 8 + 4]);
#pragma unroll
            for (int i = 0; i < 8; i++)
#pragma unroll
                for (int j = 0; j < 8; j++)
                    acc[i][j] = fmaf(av[i], bv[j], acc[i][j]);
        }
    }

    // Epilogue: scatter (token t, outdim o) -> [b*16+h][s][hd]
    const int cb = n0 + tx * 8;      // 8 consecutive cols, never cross a head (64 | 8)
    const int h = cb >> 6;
    const int hd = cb & 63;
#pragma unroll
    for (int i = 0; i < 8; i++) {
        int t = m0 + ty * 8 + i;
        int bb = t >> 11;
        int s = t & 2047;
        float* dst = C + (((bb * NHEADS + h) * SEQ + s) << 6) + hd;
        *(float4*)dst       = make_float4(acc[i][0], acc[i][1], acc[i][2], acc[i][3]);
        *(float4*)(dst + 4) = make_float4(acc[i][4], acc[i][5], acc[i][6], acc[i][7]);
    }
}

__global__ __launch_bounds__(256, 2) void sgemm_out_kernel(
    const float* __restrict__ Wo,
    float* __restrict__ out)
{
    __shared__ __align__(16) float As[8][128];
    __shared__ __align__(16) float Bs[8][128];

    const int tid = threadIdx.x;
    const int m0 = blockIdx.y * 128;
    const int n0 = blockIdx.x * 128;
    const int lr = tid >> 1;
    const int lk = (tid & 1) << 2;
    const int ty = tid >> 4;
    const int tx = tid & 15;

    const float* ap = g_O + (m0 + lr) * DMODEL + lk;
    const float* bp = Wo + (n0 + lr) * DMODEL + lk;

    float acc[8][8];
#pragma unroll
    for (int i = 0; i < 8; i++)
#pragma unroll
        for (int j = 0; j < 8; j++) acc[i][j] = 0.f;

    for (int k0 = 0; k0 < DMODEL; k0 += 8) {
        float4 a = *(const float4*)(ap + k0);
        float4 b = *(const float4*)(bp + k0);
        __syncthreads();
        As[lk + 0][lr] = a.x; As[lk + 1][lr] = a.y;
        As[lk + 2][lr] = a.z; As[lk + 3][lr] = a.w;
        Bs[lk + 0][lr] = b.x; Bs[lk + 1][lr] = b.y;
        Bs[lk + 2][lr] = b.z; Bs[lk + 3][lr] = b.w;
        __syncthreads();
#pragma unroll
        for (int kk = 0; kk < 8; kk++) {
            float av[8], bv[8];
            *(float4*)(av)     = *(const float4*)(&As[kk][ty * 8]);
            *(float4*)(av + 4) = *(const float4*)(&As[kk][ty * 8 + 4]);
            *(float4*)(bv)     = *(const float4*)(&Bs[kk][tx * 8]);
            *(float4*)(bv + 4) = *(const float4*)(&Bs[kk][tx * 8 + 4]);
#pragma unroll
            for (int i = 0; i < 8; i++)
#pragma unroll
                for (int j = 0; j < 8; j++)
                    acc[i][j] = fmaf(av[i], bv[j], acc[i][j]);
        }
    }

#pragma unroll
    for (int i = 0; i < 8; i++) {
        int t = m0 + ty * 8 + i;
        float* dst = out + t * DMODEL + n0 + tx * 8;
        *(float4*)dst       = make_float4(acc[i][0], acc[i][1], acc[i][2], acc[i][3]);
        *(float4*)(dst + 4) = make_float4(acc[i][4], acc[i][5], acc[i][6], acc[i][7]);
    }
}

// ---------------------------------------------------------------------------
// Flash attention (causal), fp32. Br=Bc=64, Hd=64, 128 threads.
// Thread (ty in [0,16), tx in [0,8)): owns rows 4*ty..+3, S-cols / O-dims 8*tx..+7.
// Smem: Qs [d][r], KP (K tile [d][c], later P tile [r][c]), Vs [j][d]. 48 KB total.
// ---------------------------------------------------------------------------

__global__ __launch_bounds__(128) void flash_kernel()
{
    __shared__ __align__(16) float Qs[64 * 64];
    __shared__ __align__(16) float KP[64 * 64];
    __shared__ __align__(16) float Vs[64 * 64];

    const int tid = threadIdx.x;
    const int qt = blockIdx.x;   // query tile 0..31
    const int bh = blockIdx.y;   // 0..31
    const int q0 = qt * 64;

    const float* qbase = g_Q + (bh * SEQ + q0) * 64;
    const float* kbase = g_K + bh * SEQ * 64;
    const float* vbase = g_V + bh * SEQ * 64;

    // Load Q tile transposed [d][r], pre-scaled by 1/sqrt(64)
    {
        int row = tid >> 1;
        int d0 = (tid & 1) * 32;
        const float* qp = qbase + row * 64 + d0;
#pragma unroll
        for (int u = 0; u < 8; u++) {
            float4 v = *(const float4*)(qp + u * 4);
            Qs[(d0 + u * 4 + 0) * 64 + row] = v.x * 0.125f;
            Qs[(d0 + u * 4 + 1) * 64 + row] = v.y * 0.125f;
            Qs[(d0 + u * 4 + 2) * 64 + row] = v.z * 0.125f;
            Qs[(d0 + u * 4 + 3) * 64 + row] = v.w * 0.125f;
        }
    }

    const int ty = tid >> 3;
    const int tx = tid & 7;

    float m[4], l[4], o[4][8];
#pragma unroll
    for (int i = 0; i < 4; i++) {
        m[i] = neg_inf();
        l[i] = 0.f;
#pragma unroll
        for (int j = 0; j < 8; j++) o[i][j] = 0.f;
    }

    for (int t = 0; t <= qt; t++) {
        __syncthreads();   // prev iter's KP/Vs reads done; Q load done (iter 0)
        {
            int row = tid >> 1;
            int d0 = (tid & 1) * 32;
            const float* kp = kbase + (t * 64 + row) * 64 + d0;
            const float* vp = vbase + (t * 64 + row) * 64 + d0;
#pragma unroll
            for (int u = 0; u < 8; u++) {
                float4 kv = *(const float4*)(kp + u * 4);
                KP[(d0 + u * 4 + 0) * 64 + row] = kv.x;
                KP[(d0 + u * 4 + 1) * 64 + row] = kv.y;
                KP[(d0 + u * 4 + 2) * 64 + row] = kv.z;
                KP[(d0 + u * 4 + 3) * 64 + row] = kv.w;
                *(float4*)(&Vs[row * 64 + d0 + u * 4]) = *(const float4*)(vp + u * 4);
            }
        }
        __syncthreads();

        // S = Q K^T (per-thread 4x8)
        float s[4][8];
#pragma unroll
        for (int i = 0; i < 4; i++)
#pragma unroll
            for (int j = 0; j < 8; j++) s[i][j] = 0.f;

#pragma unroll 8
        for (int d = 0; d < 64; d++) {
            float qa[4], kb[8];
            *(float4*)qa       = *(const float4*)(&Qs[d * 64 + ty * 4]);
            *(float4*)kb       = *(const float4*)(&KP[d * 64 + tx * 8]);
            *(float4*)(kb + 4) = *(const float4*)(&KP[d * 64 + tx * 8 + 4]);
#pragma unroll
            for (int i = 0; i < 4; i++)
#pragma unroll
                for (int j = 0; j < 8; j++)
                    s[i][j] = fmaf(qa[i], kb[j], s[i][j]);
        }

        if (t == qt) {
#pragma unroll
            for (int i = 0; i < 4; i++)
#pragma unroll
                for (int j = 0; j < 8; j++)
                    if (tx * 8 + j > ty * 4 + i) s[i][j] = neg_inf();
        }

        __syncthreads();   // everyone done reading KP as K tile

        // Online softmax per row; P written into KP as [r][c]
#pragma unroll
        for (int i = 0; i < 4; i++) {
            float mx = s[i][0];
#pragma unroll
            for (int j = 1; j < 8; j++) mx = fmaxf(mx, s[i][j]);
            mx = fmaxf(mx, __shfl_xor_sync(0xffffffffu, mx, 1));
            mx = fmaxf(mx, __shfl_xor_sync(0xffffffffu, mx, 2));
            mx = fmaxf(mx, __shfl_xor_sync(0xffffffffu, mx, 4));
            float mnew = fmaxf(m[i], mx);
            float corr = __expf(m[i] - mnew);
            float rs = 0.f;
#pragma unroll
            for (int j = 0; j < 8; j++) {
                s[i][j] = __expf(s[i][j] - mnew);
                rs += s[i][j];
            }
            rs += __shfl_xor_sync(0xffffffffu, rs, 1);
            rs += __shfl_xor_sync(0xffffffffu, rs, 2);
            rs += __shfl_xor_sync(0xffffffffu, rs, 4);
            l[i] = l[i] * corr + rs;
            m[i] = mnew;
#pragma unroll
            for (int j = 0; j < 8; j++) o[i][j] *= corr;
            *(float4*)(&KP[(ty * 4 + i) * 64 + tx * 8])     =
                make_float4(s[i][0], s[i][1], s[i][2], s[i][3]);
            *(float4*)(&KP[(ty * 4 + i) * 64 + tx * 8 + 4]) =
                make_float4(s[i][4], s[i][5], s[i][6], s[i][7]);
        }
        __syncthreads();   // P tile complete

        // O += P V
#pragma unroll 4
        for (int j0 = 0; j0 < 64; j0 += 4) {
            float pa[4][4];
#pragma unroll
            for (int i = 0; i < 4; i++)
                *(float4*)pa[i] = *(const float4*)(&KP[(ty * 4 + i) * 64 + j0]);
#pragma unroll
            for (int u = 0; u < 4; u++) {
                float vv[8];
                *(float4*)vv       = *(const float4*)(&Vs[(j0 + u) * 64 + tx * 8]);
                *(float4*)(vv + 4) = *(const float4*)(&Vs[(j0 + u) * 64 + tx * 8 + 4]);
#pragma unroll
                for (int i = 0; i < 4; i++)
#pragma unroll
                    for (int jj = 0; jj < 8; jj++)
                        o[i][jj] = fmaf(pa[i][u], vv[jj], o[i][jj]);
            }
        }
    }

    // Epilogue: normalize and write to [token][dmodel] scratch
    const int bb = bh >> 4;
    const int h = bh & 15;
#pragma unroll
    for (int i = 0; i < 4; i++) {
        float inv = 1.f / l[i];
        int row = q0 + ty * 4 + i;
        float* dst = g_O + (bb * SEQ + row) * DMODEL + h * 64 + tx * 8;
        *(float4*)dst       = make_float4(o[i][0] * inv, o[i][1] * inv,
                                          o[i][2] * inv, o[i][3] * inv);
        *(float4*)(dst + 4) = make_float4(o[i][4] * inv, o[i][5] * inv,
                                          o[i][6] * inv, o[i][7] * inv);
    }
}

// ---------------------------------------------------------------------------

extern "C" void kernel_launch(void* const* d_in, const int* in_sizes, int n_in,
                              void* d_out, int out_size)
{
    (void)in_sizes; (void)n_in; (void)out_size;
    const float* x  = (const float*)d_in[0];
    const float* Wq = (const float*)d_in[1];
    const float* Wk = (const float*)d_in[2];
    const float* Wv = (const float*)d_in[3];
    const float* Wo = (const float*)d_in[4];
    float* out = (float*)d_out;

    dim3 gqkv(DMODEL / 128, TOKENS / 128, 3);   // (8, 32, 3)
    sgemm_qkv_kernel<<<gqkv, 256>>>(x, Wq, Wk, Wv);

    dim3 gatt(SEQ / 64, 2 * NHEADS);            // (32, 32)
    flash_kernel<<<gatt, 128>>>();

    dim3 gout(DMODEL / 128, TOKENS / 128, 1);   // (8, 32)
    sgemm_out_kernel<<<gout, 256>>>(Wo, out);
}

// round 3
// speedup vs baseline: 1.2752x; 1.2752x over previous
#include <cuda_runtime.h>
#include <cuda_bf16.h>
#include <cstdint>

#define TOKENS 4096
#define DMODEL 1024
#define NHEADS 16
#define SEQ 2048

// Scratch: Q,K,V in [B*H][S][64] layout; O in [token][dmodel] layout.
__device__ __align__(16) float g_Q[TOKENS * DMODEL];
__device__ __align__(16) float g_K[TOKENS * DMODEL];
__device__ __align__(16) float g_V[TOKENS * DMODEL];
__device__ __align__(16) float g_O[TOKENS * DMODEL];

__device__ __forceinline__ float neg_inf() { return __int_as_float(0xff800000u); }

__device__ __forceinline__ uint32_t smem_u32(const void* p) {
    uint32_t a;
    asm("{ .reg .u64 t; cvta.to.shared.u64 t, %1; cvt.u32.u64 %0, t; }"
        : "=r"(a) : "l"(p));
    return a;
}

__device__ __forceinline__ uint32_t pack_bf2(__nv_bfloat16 a, __nv_bfloat16 b) {
    return (uint32_t)__bfloat16_as_ushort(a) |
           ((uint32_t)__bfloat16_as_ushort(b) << 16);
}

__device__ __forceinline__ void split_pack(float a, float b,
                                           uint32_t& h, uint32_t& l) {
    __nv_bfloat16 ha = __float2bfloat16_rn(a);
    __nv_bfloat16 hb = __float2bfloat16_rn(b);
    __nv_bfloat16 la = __float2bfloat16_rn(a - __bfloat162float(ha));
    __nv_bfloat16 lb = __float2bfloat16_rn(b - __bfloat162float(hb));
    h = pack_bf2(ha, hb);
    l = pack_bf2(la, lb);
}

__device__ __forceinline__ void ldsm_x4(uint32_t* r, uint32_t addr) {
    asm volatile("ldmatrix.sync.aligned.m8n8.x4.shared.b16 {%0,%1,%2,%3}, [%4];"
                 : "=r"(r[0]), "=r"(r[1]), "=r"(r[2]), "=r"(r[3]) : "r"(addr));
}

__device__ __forceinline__ void ldsm_x2(uint32_t* r, uint32_t addr) {
    asm volatile("ldmatrix.sync.aligned.m8n8.x2.shared.b16 {%0,%1}, [%2];"
                 : "=r"(r[0]), "=r"(r[1]) : "r"(addr));
}

__device__ __forceinline__ void mma16816(float* d, const uint32_t* a,
                                         const uint32_t* b) {
    asm volatile("mma.sync.aligned.m16n8k16.row.col.f32.bf16.bf16.f32 "
                 "{%0,%1,%2,%3}, {%4,%5,%6,%7}, {%8,%9}, {%0,%1,%2,%3};"
                 : "+f"(d[0]), "+f"(d[1]), "+f"(d[2]), "+f"(d[3])
                 : "r"(a[0]), "r"(a[1]), "r"(a[2]), "r"(a[3]),
                   "r"(b[0]), "r"(b[1]));
}

// ---------------------------------------------------------------------------
// Split-bf16 HMMA GEMM: C[m][n] = sum_k A[m][k]*B[n][k], fp32-accurate.
// CTA tile 128x128, BK=32, 8 warps (2x4), warp tile 64x32 (4x4 m16n8k16).
// Smem: bf16 tiles packed 2 m-rows per 128B line, 16B-chunk XOR swizzle:
//   chunk'(r, c) = ((r&1)*4 + c) ^ ((r>>1)&7)   [c = k8-group 0..3]
// -> every ldmatrix 8-row phase hits 8 distinct 16B bank groups.
// ---------------------------------------------------------------------------

__device__ __forceinline__ uint32_t tile_off(int r, int c) {
    return (uint32_t)((r >> 1) * 128 + (((((r & 1) << 2) | c) ^ ((r >> 1) & 7)) << 4));
}

__global__ __launch_bounds__(256, 1) void gemm_mma(
    const float* __restrict__ Aext,
    const float* __restrict__ W0,
    const float* __restrict__ W1,
    const float* __restrict__ W2,
    float* __restrict__ Cout,
    int qkv_mode)
{
    // 4 x 8KB tiles = 32KB static smem
    __shared__ __align__(16) char smAh[8192];
    __shared__ __align__(16) char smAl[8192];
    __shared__ __align__(16) char smBh[8192];
    __shared__ __align__(16) char smBl[8192];

    const int tid = threadIdx.x;
    const int lane = tid & 31;
    const int wid = tid >> 5;
    const int warp_m = wid >> 2;   // 0..1
    const int warp_n = wid & 3;    // 0..3

    const float* A;
    const float* B;
    float* C;
    if (qkv_mode) {
        A = Aext;
        B = (blockIdx.z == 0) ? W0 : (blockIdx.z == 1 ? W1 : W2);
        C = (blockIdx.z == 0) ? g_Q : (blockIdx.z == 1 ? g_K : g_V);
    } else {
        A = g_O; B = W0; C = Cout;
    }
    const int m0 = blockIdx.y * 128;
    const int n0 = blockIdx.x * 128;
    const float* Ag = A + (size_t)m0 * DMODEL;
    const float* Bg = B + (size_t)n0 * DMODEL;

    const uint32_t sAh = smem_u32(smAh), sAl = smem_u32(smAl);
    const uint32_t sBh = smem_u32(smBh), sBl = smem_u32(smBl);

    float acc[4][4][4];
#pragma unroll
    for (int i = 0; i < 4; i++)
#pragma unroll
        for (int j = 0; j < 4; j++)
#pragma unroll
            for (int u = 0; u < 4; u++) acc[i][j][u] = 0.f;

    // ldmatrix per-lane addressing (precompute row indices + swizzle bases)
    const int a_mat = lane >> 3;        // 0..3: {m0-7,k0-7},{m8-15,k0-7},{m0-7,k8-15},{m8-15,k8-15}
    const int a_ri = lane & 7;
    const int a_khalf = a_mat >> 1;     // k8-group offset within kstep
    int rowA[4];
#pragma unroll
    for (int im = 0; im < 4; im++)
        rowA[im] = warp_m * 64 + im * 16 + (a_mat & 1) * 8 + a_ri;

    const int b_mat = (lane >> 3) & 1;
    const int b_ri = lane & 7;
    int rowB[4];
#pragma unroll
    for (int in = 0; in < 4; in++)
        rowB[in] = warp_n * 32 + in * 8 + b_ri;

    for (int ch = 0; ch < 32; ch++) {
        const int k0 = ch * 32;
        // Load + split-convert A and B tiles (128 rows x 32 k each)
#pragma unroll
        for (int it = 0; it < 2; it++) {
            int lin = it * 256 + tid;      // 0..511
            int r = lin >> 2;              // 0..127
            int c = lin & 3;               // k8-group
            uint32_t off = tile_off(r, c);
            {
                const float* p = Ag + (size_t)r * DMODEL + k0 + c * 8;
                float4 v0 = *(const float4*)p;
                float4 v1 = *(const float4*)(p + 4);
                uint32_t h0, h1, h2, h3, l0, l1, l2, l3;
                split_pack(v0.x, v0.y, h0, l0);
                split_pack(v0.z, v0.w, h1, l1);
                split_pack(v1.x, v1.y, h2, l2);
                split_pack(v1.z, v1.w, h3, l3);
                *(uint4*)(smAh + off) = make_uint4(h0, h1, h2, h3);
                *(uint4*)(smAl + off) = make_uint4(l0, l1, l2, l3);
            }
            {
                const float* p = Bg + (size_t)r * DMODEL + k0 + c * 8;
                float4 v0 = *(const float4*)p;
                float4 v1 = *(const float4*)(p + 4);
                uint32_t h0, h1, h2, h3, l0, l1, l2, l3;
                split_pack(v0.x, v0.y, h0, l0);
                split_pack(v0.z, v0.w, h1, l1);
                split_pack(v1.x, v1.y, h2, l2);
                split_pack(v1.z, v1.w, h3, l3);
                *(uint4*)(smBh + off) = make_uint4(h0, h1, h2, h3);
                *(uint4*)(smBl + off) = make_uint4(l0, l1, l2, l3);
            }
        }
        __syncthreads();

#pragma unroll
        for (int kk = 0; kk < 2; kk++) {
            uint32_t ah[4][4], al[4][4];
#pragma unroll
            for (int im = 0; im < 4; im++) {
                uint32_t off = tile_off(rowA[im], kk * 2 + a_khalf);
                ldsm_x4(ah[im], sAh + off);
                ldsm_x4(al[im], sAl + off);
            }
            uint32_t bh[4][2], bl[4][2];
#pragma unroll
            for (int in = 0; in < 4; in++) {
                uint32_t off = tile_off(rowB[in], kk * 2 + b_mat);
                ldsm_x2(bh[in], sBh + off);
                ldsm_x2(bl[in], sBl + off);
            }
#pragma unroll
            for (int im = 0; im < 4; im++)
#pragma unroll
                for (int in = 0; in < 4; in++) {
                    mma16816(acc[im][in], ah[im], bh[in]);
                    mma16816(acc[im][in], ah[im], bl[in]);
                    mma16816(acc[im][in], al[im], bh[in]);
                }
        }
        __syncthreads();
    }

    // Epilogue. c0,c1 at (row=groupID, col=(lane%4)*2+{0,1}); c2,c3 at row+8.
    const int gid = lane >> 2;
    const int tig = lane & 3;
#pragma unroll
    for (int im = 0; im < 4; im++) {
#pragma unroll
        for (int in = 0; in < 4; in++) {
            int row = m0 + warp_m * 64 + im * 16 + gid;
            int col = n0 + warp_n * 32 + in * 8 + tig * 2;
            if (qkv_mode) {
                int h = col >> 6, hd = col & 63;
#pragma unroll
                for (int half = 0; half < 2; half++) {
                    int rr = row + half * 8;
                    int bb = rr >> 11, s = rr & 2047;
                    float* dst = C + (((size_t)(bb * NHEADS + h) * SEQ + s) << 6) + hd;
                    dst[0] = acc[im][in][half * 2 + 0];
                    dst[1] = acc[im][in][half * 2 + 1];
                }
            } else {
#pragma unroll
                for (int half = 0; half < 2; half++) {
                    int rr = row + half * 8;
                    float* dst = C + (size_t)rr * DMODEL + col;
                    dst[0] = acc[im][in][half * 2 + 0];
                    dst[1] = acc[im][in][half * 2 + 1];
                }
            }
        }
    }
}

// ---------------------------------------------------------------------------
// Flash attention (causal), fp32. Br=Bc=64, Hd=64, 128 threads. (unchanged)
// ---------------------------------------------------------------------------

__global__ __launch_bounds__(128) void flash_kernel()
{
    __shared__ __align__(16) float Qs[64 * 64];
    __shared__ __align__(16) float KP[64 * 64];
    __shared__ __align__(16) float Vs[64 * 64];

    const int tid = threadIdx.x;
    const int qt = blockIdx.x;
    const int bh = blockIdx.y;
    const int q0 = qt * 64;

    const float* qbase = g_Q + (bh * SEQ + q0) * 64;
    const float* kbase = g_K + bh * SEQ * 64;
    const float* vbase = g_V + bh * SEQ * 64;

    {
        int row = tid >> 1;
        int d0 = (tid & 1) * 32;
        const float* qp = qbase + row * 64 + d0;
#pragma unroll
        for (int u = 0; u < 8; u++) {
            float4 v = *(const float4*)(qp + u * 4);
            Qs[(d0 + u * 4 + 0) * 64 + row] = v.x * 0.125f;
            Qs[(d0 + u * 4 + 1) * 64 + row] = v.y * 0.125f;
            Qs[(d0 + u * 4 + 2) * 64 + row] = v.z * 0.125f;
            Qs[(d0 + u * 4 + 3) * 64 + row] = v.w * 0.125f;
        }
    }

    const int ty = tid >> 3;
    const int tx = tid & 7;

    float m[4], l[4], o[4][8];
#pragma unroll
    for (int i = 0; i < 4; i++) {
        m[i] = neg_inf();
        l[i] = 0.f;
#pragma unroll
        for (int j = 0; j < 8; j++) o[i][j] = 0.f;
    }

    for (int t = 0; t <= qt; t++) {
        __syncthreads();
        {
            int row = tid >> 1;
            int d0 = (tid & 1) * 32;
            const float* kp = kbase + (t * 64 + row) * 64 + d0;
            const float* vp = vbase + (t * 64 + row) * 64 + d0;
#pragma unroll
            for (int u = 0; u < 8; u++) {
                float4 kv = *(const float4*)(kp + u * 4);
                KP[(d0 + u * 4 + 0) * 64 + row] = kv.x;
                KP[(d0 + u * 4 + 1) * 64 + row] = kv.y;
                KP[(d0 + u * 4 + 2) * 64 + row] = kv.z;
                KP[(d0 + u * 4 + 3) * 64 + row] = kv.w;
                *(float4*)(&Vs[row * 64 + d0 + u * 4]) = *(const float4*)(vp + u * 4);
            }
        }
        __syncthreads();

        float s[4][8];
#pragma unroll
        for (int i = 0; i < 4; i++)
#pragma unroll
            for (int j = 0; j < 8; j++) s[i][j] = 0.f;

#pragma unroll 8
        for (int d = 0; d < 64; d++) {
            float qa[4], kb[8];
            *(float4*)qa       = *(const float4*)(&Qs[d * 64 + ty * 4]);
            *(float4*)kb       = *(const float4*)(&KP[d * 64 + tx * 8]);
            *(float4*)(kb + 4) = *(const float4*)(&KP[d * 64 + tx * 8 + 4]);
#pragma unroll
            for (int i = 0; i < 4; i++)
#pragma unroll
                for (int j = 0; j < 8; j++)
                    s[i][j] = fmaf(qa[i], kb[j], s[i][j]);
        }

        if (t == qt) {
#pragma unroll
            for (int i = 0; i < 4; i++)
#pragma unroll
                for (int j = 0; j < 8; j++)
                    if (tx * 8 + j > ty * 4 + i) s[i][j] = neg_inf();
        }

        __syncthreads();

#pragma unroll
        for (int i = 0; i < 4; i++) {
            float mx = s[i][0];
#pragma unroll
            for (int j = 1; j < 8; j++) mx = fmaxf(mx, s[i][j]);
            mx = fmaxf(mx, __shfl_xor_sync(0xffffffffu, mx, 1));
            mx = fmaxf(mx, __shfl_xor_sync(0xffffffffu, mx, 2));
            mx = fmaxf(mx, __shfl_xor_sync(0xffffffffu, mx, 4));
            float mnew = fmaxf(m[i], mx);
            float corr = __expf(m[i] - mnew);
            float rs = 0.f;
#pragma unroll
            for (int j = 0; j < 8; j++) {
                s[i][j] = __expf(s[i][j] - mnew);
                rs += s[i][j];
            }
            rs += __shfl_xor_sync(0xffffffffu, rs, 1);
            rs += __shfl_xor_sync(0xffffffffu, rs, 2);
            rs += __shfl_xor_sync(0xffffffffu, rs, 4);
            l[i] = l[i] * corr + rs;
            m[i] = mnew;
#pragma unroll
            for (int j = 0; j < 8; j++) o[i][j] *= corr;
            *(float4*)(&KP[(ty * 4 + i) * 64 + tx * 8])     =
                make_float4(s[i][0], s[i][1], s[i][2], s[i][3]);
            *(float4*)(&KP[(ty * 4 + i) * 64 + tx * 8 + 4]) =
                make_float4(s[i][4], s[i][5], s[i][6], s[i][7]);
        }
        __syncthreads();

#pragma unroll 4
        for (int j0 = 0; j0 < 64; j0 += 4) {
            float pa[4][4];
#pragma unroll
            for (int i = 0; i < 4; i++)
                *(float4*)pa[i] = *(const float4*)(&KP[(ty * 4 + i) * 64 + j0]);
#pragma unroll
            for (int u = 0; u < 4; u++) {
                float vv[8];
                *(float4*)vv       = *(const float4*)(&Vs[(j0 + u) * 64 + tx * 8]);
                *(float4*)(vv + 4) = *(const float4*)(&Vs[(j0 + u) * 64 + tx * 8 + 4]);
#pragma unroll
                for (int i = 0; i < 4; i++)
#pragma unroll
                    for (int jj = 0; jj < 8; jj++)
                        o[i][jj] = fmaf(pa[i][u], vv[jj], o[i][jj]);
            }
        }
    }

    const int bb = bh >> 4;
    const int h = bh & 15;
#pragma unroll
    for (int i = 0; i < 4; i++) {
        float inv = 1.f / l[i];
        int row = q0 + ty * 4 + i;
        float* dst = g_O + (bb * SEQ + row) * DMODEL + h * 64 + tx * 8;
        *(float4*)dst       = make_float4(o[i][0] * inv, o[i][1] * inv,
                                          o[i][2] * inv, o[i][3] * inv);
        *(float4*)(dst + 4) = make_float4(o[i][4] * inv, o[i][5] * inv,
                                          o[i][6] * inv, o[i][7] * inv);
    }
}

// ---------------------------------------------------------------------------

extern "C" void kernel_launch(void* const* d_in, const int* in_sizes, int n_in,
                              void* d_out, int out_size)
{
    (void)in_sizes; (void)n_in; (void)out_size;
    const float* x  = (const float*)d_in[0];
    const float* Wq = (const float*)d_in[1];
    const float* Wk = (const float*)d_in[2];
    const float* Wv = (const float*)d_in[3];
    const float* Wo = (const float*)d_in[4];
    float* out = (float*)d_out;

    dim3 gqkv(DMODEL / 128, TOKENS / 128, 3);   // (8, 32, 3)
    gemm_mma<<<gqkv, 256>>>(x, Wq, Wk, Wv, nullptr, 1);

    dim3 gatt(SEQ / 64, 2 * NHEADS);            // (32, 32)
    flash_kernel<<<gatt, 128>>>();

    dim3 gout(DMODEL / 128, TOKENS / 128, 1);   // (8, 32)
    gemm_mma<<<gout, 256>>>(nullptr, Wo, nullptr, nullptr, out, 0);
}

// round 5
// speedup vs baseline: 2.1848x; 1.7134x over previous
#include <cuda_runtime.h>
#include <cuda_bf16.h>
#include <cstdint>

#define TOKENS 4096
#define DMODEL 1024
#define NHEADS 16
#define SEQ 2048

__device__ __align__(16) float g_Q[TOKENS * DMODEL];
__device__ __align__(16) float g_K[TOKENS * DMODEL];
__device__ __align__(16) float g_V[TOKENS * DMODEL];
__device__ __align__(16) float g_O[TOKENS * DMODEL];

__device__ __forceinline__ float neg_inf() { return __int_as_float(0xff800000u); }

__device__ __forceinline__ uint32_t smem_u32(const void* p) {
    uint32_t a;
    asm("{ .reg .u64 t; cvta.to.shared.u64 t, %1; cvt.u32.u64 %0, t; }"
        : "=r"(a) : "l"(p));
    return a;
}

__device__ __forceinline__ uint32_t pack_bf2(__nv_bfloat16 a, __nv_bfloat16 b) {
    return (uint32_t)__bfloat16_as_ushort(a) |
           ((uint32_t)__bfloat16_as_ushort(b) << 16);
}

__device__ __forceinline__ void split_pack(float a, float b,
                                           uint32_t& h, uint32_t& l) {
    __nv_bfloat16 ha = __float2bfloat16_rn(a);
    __nv_bfloat16 hb = __float2bfloat16_rn(b);
    __nv_bfloat16 la = __float2bfloat16_rn(a - __bfloat162float(ha));
    __nv_bfloat16 lb = __float2bfloat16_rn(b - __bfloat162float(hb));
    h = pack_bf2(ha, hb);
    l = pack_bf2(la, lb);
}

__device__ __forceinline__ void ldsm_x4(uint32_t* r, uint32_t addr) {
    asm volatile("ldmatrix.sync.aligned.m8n8.x4.shared.b16 {%0,%1,%2,%3}, [%4];"
                 : "=r"(r[0]), "=r"(r[1]), "=r"(r[2]), "=r"(r[3]) : "r"(addr));
}

__device__ __forceinline__ void ldsm_x2(uint32_t* r, uint32_t addr) {
    asm volatile("ldmatrix.sync.aligned.m8n8.x2.shared.b16 {%0,%1}, [%2];"
                 : "=r"(r[0]), "=r"(r[1]) : "r"(addr));
}

__device__ __forceinline__ void mma16816(float* d, const uint32_t* a,
                                         const uint32_t* b) {
    asm volatile("mma.sync.aligned.m16n8k16.row.col.f32.bf16.bf16.f32 "
                 "{%0,%1,%2,%3}, {%4,%5,%6,%7}, {%8,%9}, {%0,%1,%2,%3};"
                 : "+f"(d[0]), "+f"(d[1]), "+f"(d[2]), "+f"(d[3])
                 : "r"(a[0]), "r"(a[1]), "r"(a[2]), "r"(a[3]),
                   "r"(b[0]), "r"(b[1]));
}

// ---------------------------------------------------------------------------
// Split-bf16 HMMA GEMM (unchanged from round 3 — passed, 1.4e-5)
// ---------------------------------------------------------------------------

__device__ __forceinline__ uint32_t tile_off(int r, int c) {
    return (uint32_t)((r >> 1) * 128 + (((((r & 1) << 2) | c) ^ ((r >> 1) & 7)) << 4));
}

__global__ __launch_bounds__(256, 1) void gemm_mma(
    const float* __restrict__ Aext,
    const float* __restrict__ W0,
    const float* __restrict__ W1,
    const float* __restrict__ W2,
    float* __restrict__ Cout,
    int qkv_mode)
{
    __shared__ __align__(16) char smAh[8192];
    __shared__ __align__(16) char smAl[8192];
    __shared__ __align__(16) char smBh[8192];
    __shared__ __align__(16) char smBl[8192];

    const int tid = threadIdx.x;
    const int lane = tid & 31;
    const int wid = tid >> 5;
    const int warp_m = wid >> 2;
    const int warp_n = wid & 3;

    const float* A;
    const float* B;
    float* C;
    if (qkv_mode) {
        A = Aext;
        B = (blockIdx.z == 0) ? W0 : (blockIdx.z == 1 ? W1 : W2);
        C = (blockIdx.z == 0) ? g_Q : (blockIdx.z == 1 ? g_K : g_V);
    } else {
        A = g_O; B = W0; C = Cout;
    }
    const int m0 = blockIdx.y * 128;
    const int n0 = blockIdx.x * 128;
    const float* Ag = A + (size_t)m0 * DMODEL;
    const float* Bg = B + (size_t)n0 * DMODEL;

    const uint32_t sAh = smem_u32(smAh), sAl = smem_u32(smAl);
    const uint32_t sBh = smem_u32(smBh), sBl = smem_u32(smBl);

    float acc[4][4][4];
#pragma unroll
    for (int i = 0; i < 4; i++)
#pragma unroll
        for (int j = 0; j < 4; j++)
#pragma unroll
            for (int u = 0; u < 4; u++) acc[i][j][u] = 0.f;

    const int a_mat = lane >> 3;
    const int a_ri = lane & 7;
    const int a_khalf = a_mat >> 1;
    int rowA[4];
#pragma unroll
    for (int im = 0; im < 4; im++)
        rowA[im] = warp_m * 64 + im * 16 + (a_mat & 1) * 8 + a_ri;

    const int b_mat = (lane >> 3) & 1;
    const int b_ri = lane & 7;
    int rowB[4];
#pragma unroll
    for (int in = 0; in < 4; in++)
        rowB[in] = warp_n * 32 + in * 8 + b_ri;

    for (int ch = 0; ch < 32; ch++) {
        const int k0 = ch * 32;
#pragma unroll
        for (int it = 0; it < 2; it++) {
            int lin = it * 256 + tid;
            int r = lin >> 2;
            int c = lin & 3;
            uint32_t off = tile_off(r, c);
            {
                const float* p = Ag + (size_t)r * DMODEL + k0 + c * 8;
                float4 v0 = *(const float4*)p;
                float4 v1 = *(const float4*)(p + 4);
                uint32_t h0, h1, h2, h3, l0, l1, l2, l3;
                split_pack(v0.x, v0.y, h0, l0);
                split_pack(v0.z, v0.w, h1, l1);
                split_pack(v1.x, v1.y, h2, l2);
                split_pack(v1.z, v1.w, h3, l3);
                *(uint4*)(smAh + off) = make_uint4(h0, h1, h2, h3);
                *(uint4*)(smAl + off) = make_uint4(l0, l1, l2, l3);
            }
            {
                const float* p = Bg + (size_t)r * DMODEL + k0 + c * 8;
                float4 v0 = *(const float4*)p;
                float4 v1 = *(const float4*)(p + 4);
                uint32_t h0, h1, h2, h3, l0, l1, l2, l3;
                split_pack(v0.x, v0.y, h0, l0);
                split_pack(v0.z, v0.w, h1, l1);
                split_pack(v1.x, v1.y, h2, l2);
                split_pack(v1.z, v1.w, h3, l3);
                *(uint4*)(smBh + off) = make_uint4(h0, h1, h2, h3);
                *(uint4*)(smBl + off) = make_uint4(l0, l1, l2, l3);
            }
        }
        __syncthreads();

#pragma unroll
        for (int kk = 0; kk < 2; kk++) {
            uint32_t ah[4][4], al[4][4];
#pragma unroll
            for (int im = 0; im < 4; im++) {
                uint32_t off = tile_off(rowA[im], kk * 2 + a_khalf);
                ldsm_x4(ah[im], sAh + off);
                ldsm_x4(al[im], sAl + off);
            }
            uint32_t bh[4][2], bl[4][2];
#pragma unroll
            for (int in = 0; in < 4; in++) {
                uint32_t off = tile_off(rowB[in], kk * 2 + b_mat);
                ldsm_x2(bh[in], sBh + off);
                ldsm_x2(bl[in], sBl + off);
            }
#pragma unroll
            for (int im = 0; im < 4; im++)
#pragma unroll
                for (int in = 0; in < 4; in++) {
                    mma16816(acc[im][in], ah[im], bh[in]);
                    mma16816(acc[im][in], ah[im], bl[in]);
                    mma16816(acc[im][in], al[im], bh[in]);
                }
        }
        __syncthreads();
    }

    const int gid = lane >> 2;
    const int tig = lane & 3;
#pragma unroll
    for (int im = 0; im < 4; im++) {
#pragma unroll
        for (int in = 0; in < 4; in++) {
            int row = m0 + warp_m * 64 + im * 16 + gid;
            int col = n0 + warp_n * 32 + in * 8 + tig * 2;
            if (qkv_mode) {
                int h = col >> 6, hd = col & 63;
#pragma unroll
                for (int half = 0; half < 2; half++) {
                    int rr = row + half * 8;
                    int bb = rr >> 11, s = rr & 2047;
                    float* dst = C + (((size_t)(bb * NHEADS + h) * SEQ + s) << 6) + hd;
                    dst[0] = acc[im][in][half * 2 + 0];
                    dst[1] = acc[im][in][half * 2 + 1];
                }
            } else {
#pragma unroll
                for (int half = 0; half < 2; half++) {
                    int rr = row + half * 8;
                    float* dst = C + (size_t)rr * DMODEL + col;
                    dst[0] = acc[im][in][half * 2 + 0];
                    dst[1] = acc[im][in][half * 2 + 1];
                }
            }
        }
    }
}

// ---------------------------------------------------------------------------
// Flash attention (causal), split-bf16 HMMA. Br=Bc=64, Hd=64, 4 warps.
// Smem rows = 64 bf16 = 128B; swizzle: 16B chunk c at row r -> c ^ (r&7).
// Q/K: [row][d] hi+lo. Vt: [d][s] hi+lo (transposed on fill).
// Scores/P/O live in register c-fragments (warp tile 16 rows x 64 cols).
// ---------------------------------------------------------------------------

__device__ __forceinline__ uint32_t fl_off(int r, int c) {
    return (uint32_t)(r * 128 + ((c ^ (r & 7)) << 4));
}

__global__ __launch_bounds__(128) void flash_mma()
{
    __shared__ __align__(16) char sQh[8192];
    __shared__ __align__(16) char sQl[8192];
    __shared__ __align__(16) char sKh[8192];
    __shared__ __align__(16) char sKl[8192];
    __shared__ __align__(16) char sVh[8192];   // Vt hi: [d][s]
    __shared__ __align__(16) char sVl[8192];   // Vt lo

    const int tid = threadIdx.x;
    const int lane = tid & 31;
    const int wq = tid >> 5;       // warp: q-rows wq*16 .. +15
    const int qt = blockIdx.x;     // query tile 0..31
    const int bh = blockIdx.y;
    const int q0 = qt * 64;

    const float* qbase = g_Q + (size_t)(bh * SEQ + q0) * 64;
    const float* kbase = g_K + (size_t)bh * SEQ * 64;
    const float* vbase = g_V + (size_t)bh * SEQ * 64;

    const uint32_t aQh = smem_u32(sQh), aQl = smem_u32(sQl);
    const uint32_t aKh = smem_u32(sKh), aKl = smem_u32(sKl);
    const uint32_t aVh = smem_u32(sVh), aVl = smem_u32(sVl);

    // ---- Fill Q (pre-scaled by 0.125), rows [64][64] hi/lo ----
    {
        int r = tid >> 1;
        int d0 = (tid & 1) * 32;
        const float* qp = qbase + r * 64 + d0;
#pragma unroll
        for (int u = 0; u < 8; u++) {
            float4 v = *(const float4*)(qp + u * 4);
            v.x *= 0.125f; v.y *= 0.125f; v.z *= 0.125f; v.w *= 0.125f;
            uint32_t h0, h1, l0, l1;
            split_pack(v.x, v.y, h0, l0);
            split_pack(v.z, v.w, h1, l1);
            int d = d0 + u * 4;
            uint32_t off = r * 128 + ((((d >> 3) ^ (r & 7))) << 4) + ((d & 7) * 2);
            *(uint2*)(sQh + off) = make_uint2(h0, h1);
            *(uint2*)(sQl + off) = make_uint2(l0, l1);
        }
    }

    // Fragment addressing (same mapping as gemm_mma, which is validated)
    const int a_mat = lane >> 3;
    const int a_khalf = a_mat >> 1;
    const int rowA = wq * 16 + (a_mat & 1) * 8 + (lane & 7);
    const int b_mat = (lane >> 3) & 1;
    const int b_ri = lane & 7;
    const int gid = lane >> 2;
    const int tig = lane & 3;

    float m[2], l[2], o[8][4], s[8][4];
#pragma unroll
    for (int i = 0; i < 2; i++) { m[i] = neg_inf(); l[i] = 0.f; }
#pragma unroll
    for (int j = 0; j < 8; j++)
#pragma unroll
        for (int u = 0; u < 4; u++) o[j][u] = 0.f;

    for (int t = 0; t <= qt; t++) {
        __syncthreads();
        // ---- Fill K [s][d] hi/lo ----
        {
            int r = tid >> 1;
            int d0 = (tid & 1) * 32;
            const float* kp = kbase + (size_t)(t * 64 + r) * 64 + d0;
#pragma unroll
            for (int u = 0; u < 8; u++) {
                float4 v = *(const float4*)(kp + u * 4);
                uint32_t h0, h1, l0, l1;
                split_pack(v.x, v.y, h0, l0);
                split_pack(v.z, v.w, h1, l1);
                int d = d0 + u * 4;
                uint32_t off = r * 128 + ((((d >> 3) ^ (r & 7))) << 4) + ((d & 7) * 2);
                *(uint2*)(sKh + off) = make_uint2(h0, h1);
                *(uint2*)(sKl + off) = make_uint2(l0, l1);
            }
        }
        // ---- Fill Vt [d][s] hi/lo: thread = (s-pair sp, d-group dg) ----
        {
            int sp = tid & 31;
            int dg = tid >> 5;
            const float* vp0 = vbase + (size_t)(t * 64 + 2 * sp) * 64 + dg * 16;
            const float* vp1 = vp0 + 64;
#pragma unroll
            for (int u = 0; u < 4; u++) {
                float4 v0 = *(const float4*)(vp0 + u * 4);
                float4 v1 = *(const float4*)(vp1 + u * 4);
                float e0[4] = {v0.x, v0.y, v0.z, v0.w};
                float e1[4] = {v1.x, v1.y, v1.z, v1.w};
#pragma unroll
                for (int e = 0; e < 4; e++) {
                    int d = dg * 16 + u * 4 + e;
                    uint32_t h, lo;
                    split_pack(e0[e], e1[e], h, lo);
                    uint32_t off = d * 128 + ((((sp >> 2) ^ (d & 7))) << 4) + ((sp & 3) * 4);
                    *(uint32_t*)(sVh + off) = h;
                    *(uint32_t*)(sVl + off) = lo;
                }
            }
        }
        __syncthreads();

        // ---- S = Q K^T (contraction over d, 4 k-steps) ----
#pragma unroll
        for (int j = 0; j < 8; j++)
#pragma unroll
            for (int u = 0; u < 4; u++) s[j][u] = 0.f;

#pragma unroll
        for (int kk = 0; kk < 4; kk++) {
            uint32_t ah[4], al[4];
            uint32_t offa = fl_off(rowA, kk * 2 + a_khalf);
            ldsm_x4(ah, aQh + offa);
            ldsm_x4(al, aQl + offa);
#pragma unroll
            for (int j = 0; j < 8; j++) {
                uint32_t bhf[2], blf[2];
                uint32_t offb = fl_off(j * 8 + b_ri, kk * 2 + b_mat);
                ldsm_x2(bhf, aKh + offb);
                ldsm_x2(blf, aKl + offb);
                mma16816(s[j], ah, bhf);
                mma16816(s[j], ah, blf);
                mma16816(s[j], al, bhf);
            }
        }

        // ---- Causal mask on diagonal tile ----
        if (t == qt) {
#pragma unroll
            for (int j = 0; j < 8; j++) {
#pragma unroll
                for (int u = 0; u < 4; u++) {
                    int row = wq * 16 + (u >> 1) * 8 + gid;
                    int col = j * 8 + tig * 2 + (u & 1);
                    if (col > row) s[j][u] = neg_inf();
                }
            }
        }

        // ---- Online softmax (rows g and g+8; reduce over tig via shfl) ----
#pragma unroll
        for (int i = 0; i < 2; i++) {
            float mx = neg_inf();
#pragma unroll
            for (int j = 0; j < 8; j++) {
                mx = fmaxf(mx, s[j][i * 2]);
                mx = fmaxf(mx, s[j][i * 2 + 1]);
            }
            mx = fmaxf(mx, __shfl_xor_sync(0xffffffffu, mx, 1));
            mx = fmaxf(mx, __shfl_xor_sync(0xffffffffu, mx, 2));
            float mnew = fmaxf(m[i], mx);
            float corr = __expf(m[i] - mnew);
            float rs = 0.f;
#pragma unroll
            for (int j = 0; j < 8; j++) {
                float e0 = __expf(s[j][i * 2] - mnew);
                float e1 = __expf(s[j][i * 2 + 1] - mnew);
                s[j][i * 2] = e0;
                s[j][i * 2 + 1] = e1;
                rs += e0 + e1;
            }
            rs += __shfl_xor_sync(0xffffffffu, rs, 1);
            rs += __shfl_xor_sync(0xffffffffu, rs, 2);
            l[i] = l[i] * corr + rs;
            m[i] = mnew;
#pragma unroll
            for (int j = 0; j < 8; j++) {
                o[j][i * 2] *= corr;
                o[j][i * 2 + 1] *= corr;
            }
        }

        // ---- O += P Vt (contraction over s). P c-frags -> A-frags in regs ----
#pragma unroll
        for (int kk = 0; kk < 4; kk++) {
            uint32_t ph[4], pl[4];
#pragma unroll
            for (int half = 0; half < 2; half++) {
                const float* sv = s[2 * kk + half];
                split_pack(sv[0], sv[1], ph[half * 2], pl[half * 2]);
                split_pack(sv[2], sv[3], ph[half * 2 + 1], pl[half * 2 + 1]);
            }
#pragma unroll
            for (int j = 0; j < 8; j++) {
                uint32_t vhf[2], vlf[2];
                uint32_t offv = fl_off(j * 8 + b_ri, kk * 2 + b_mat);
                ldsm_x2(vhf, aVh + offv);
                ldsm_x2(vlf, aVl + offv);
                mma16816(o[j], ph, vhf);
                mma16816(o[j], ph, vlf);
                mma16816(o[j], pl, vhf);
            }
        }
    }

    // ---- Epilogue: normalize, write [token][dmodel] ----
    const int bb = bh >> 4;
    const int h = bh & 15;
    float inv0 = 1.f / l[0];
    float inv1 = 1.f / l[1];
#pragma unroll
    for (int j = 0; j < 8; j++) {
        int col = h * 64 + j * 8 + tig * 2;
        int r0 = q0 + wq * 16 + gid;
        float* d0 = g_O + (size_t)(bb * SEQ + r0) * DMODEL + col;
        d0[0] = o[j][0] * inv0;
        d0[1] = o[j][1] * inv0;
        float* d1 = g_O + (size_t)(bb * SEQ + r0 + 8) * DMODEL + col;
        d1[0] = o[j][2] * inv1;
        d1[1] = o[j][3] * inv1;
    }
}

// ---------------------------------------------------------------------------

extern "C" void kernel_launch(void* const* d_in, const int* in_sizes, int n_in,
                              void* d_out, int out_size)
{
    (void)in_sizes; (void)n_in; (void)out_size;
    const float* x  = (const float*)d_in[0];
    const float* Wq = (const float*)d_in[1];
    const float* Wk = (const float*)d_in[2];
    const float* Wv = (const float*)d_in[3];
    const float* Wo = (const float*)d_in[4];
    float* out = (float*)d_out;

    dim3 gqkv(DMODEL / 128, TOKENS / 128, 3);
    gemm_mma<<<gqkv, 256>>>(x, Wq, Wk, Wv, nullptr, 1);

    dim3 gatt(SEQ / 64, 2 * NHEADS);
    flash_mma<<<gatt, 128>>>();

    dim3 gout(DMODEL / 128, TOKENS / 128, 1);
    gemm_mma<<<gout, 256>>>(nullptr, Wo, nullptr, nullptr, out, 0);
}

// round 7
// speedup vs baseline: 3.0482x; 1.3952x over previous
#include <cuda_runtime.h>
#include <cuda_bf16.h>
#include <cstdint>

#define TOKENS 4096
#define DMODEL 1024
#define NHEADS 16
#define SEQ 2048

// Persistent split-bf16 copies (hi/lo) of inputs and intermediates.
__device__ __align__(16) __nv_bfloat16 g_Xh[TOKENS * DMODEL];
__device__ __align__(16) __nv_bfloat16 g_Xl[TOKENS * DMODEL];
__device__ __align__(16) __nv_bfloat16 g_Wqh[DMODEL * DMODEL];
__device__ __align__(16) __nv_bfloat16 g_Wql[DMODEL * DMODEL];
__device__ __align__(16) __nv_bfloat16 g_Wkh[DMODEL * DMODEL];
__device__ __align__(16) __nv_bfloat16 g_Wkl[DMODEL * DMODEL];
__device__ __align__(16) __nv_bfloat16 g_Wvh[DMODEL * DMODEL];
__device__ __align__(16) __nv_bfloat16 g_Wvl[DMODEL * DMODEL];
__device__ __align__(16) __nv_bfloat16 g_Woh[DMODEL * DMODEL];
__device__ __align__(16) __nv_bfloat16 g_Wol[DMODEL * DMODEL];
// Q (pre-scaled), K, V in [B*H][S][64] split-bf16; O in [token][dmodel] split-bf16.
__device__ __align__(16) __nv_bfloat16 g_Qh[TOKENS * DMODEL];
__device__ __align__(16) __nv_bfloat16 g_Ql[TOKENS * DMODEL];
__device__ __align__(16) __nv_bfloat16 g_Kh[TOKENS * DMODEL];
__device__ __align__(16) __nv_bfloat16 g_Kl[TOKENS * DMODEL];
__device__ __align__(16) __nv_bfloat16 g_Vh[TOKENS * DMODEL];
__device__ __align__(16) __nv_bfloat16 g_Vl[TOKENS * DMODEL];
__device__ __align__(16) __nv_bfloat16 g_Oh[TOKENS * DMODEL];
__device__ __align__(16) __nv_bfloat16 g_Ol[TOKENS * DMODEL];

__device__ __forceinline__ float neg_inf() { return __int_as_float(0xff800000u); }

__device__ __forceinline__ uint32_t smem_u32(const void* p) {
    uint32_t a;
    asm("{ .reg .u64 t; cvta.to.shared.u64 t, %1; cvt.u32.u64 %0, t; }"
        : "=r"(a) : "l"(p));
    return a;
}

__device__ __forceinline__ uint32_t pack_bf2(__nv_bfloat16 a, __nv_bfloat16 b) {
    return (uint32_t)__bfloat16_as_ushort(a) |
           ((uint32_t)__bfloat16_as_ushort(b) << 16);
}

__device__ __forceinline__ void split_pack(float a, float b,
                                           uint32_t& h, uint32_t& l) {
    __nv_bfloat16 ha = __float2bfloat16_rn(a);
    __nv_bfloat16 hb = __float2bfloat16_rn(b);
    __nv_bfloat16 la = __float2bfloat16_rn(a - __bfloat162float(ha));
    __nv_bfloat16 lb = __float2bfloat16_rn(b - __bfloat162float(hb));
    h = pack_bf2(ha, hb);
    l = pack_bf2(la, lb);
}

__device__ __forceinline__ void ldsm_x4(uint32_t* r, uint32_t addr) {
    asm volatile("ldmatrix.sync.aligned.m8n8.x4.shared.b16 {%0,%1,%2,%3}, [%4];"
                 : "=r"(r[0]), "=r"(r[1]), "=r"(r[2]), "=r"(r[3]) : "r"(addr));
}

__device__ __forceinline__ void ldsm_x2(uint32_t* r, uint32_t addr) {
    asm volatile("ldmatrix.sync.aligned.m8n8.x2.shared.b16 {%0,%1}, [%2];"
                 : "=r"(r[0]), "=r"(r[1]) : "r"(addr));
}

__device__ __forceinline__ void mma16816(float* d, const uint32_t* a,
                                         const uint32_t* b) {
    asm volatile("mma.sync.aligned.m16n8k16.row.col.f32.bf16.bf16.f32 "
                 "{%0,%1,%2,%3}, {%4,%5,%6,%7}, {%8,%9}, {%0,%1,%2,%3};"
                 : "+f"(d[0]), "+f"(d[1]), "+f"(d[2]), "+f"(d[3])
                 : "r"(a[0]), "r"(a[1]), "r"(a[2]), "r"(a[3]),
                   "r"(b[0]), "r"(b[1]));
}

__device__ __forceinline__ void cp16(uint32_t saddr, const void* gaddr) {
    asm volatile("cp.async.cg.shared.global [%0], [%1], 16;"
                 :: "r"(saddr), "l"(gaddr));
}

// ---------------------------------------------------------------------------
// Pre-pass: split fp32 sources into bf16 hi/lo.
// blockIdx.y: 0=x (4M elems), 1..4 = Wq,Wk,Wv,Wo (1M each).
// ---------------------------------------------------------------------------

__global__ void convert_split(const float* __restrict__ x,
                              const float* __restrict__ Wq,
                              const float* __restrict__ Wk,
                              const float* __restrict__ Wv,
                              const float* __restrict__ Wo)
{
    const float* src;
    __nv_bfloat16 *dh, *dl;
    int n;
    switch (blockIdx.y) {
        case 0: src = x;  dh = g_Xh;  dl = g_Xl;  n = TOKENS * DMODEL; break;
        case 1: src = Wq; dh = g_Wqh; dl = g_Wql; n = DMODEL * DMODEL; break;
        case 2: src = Wk; dh = g_Wkh; dl = g_Wkl; n = DMODEL * DMODEL; break;
        case 3: src = Wv; dh = g_Wvh; dl = g_Wvl; n = DMODEL * DMODEL; break;
        default: src = Wo; dh = g_Woh; dl = g_Wol; n = DMODEL * DMODEL; break;
    }
    int i = (blockIdx.x * blockDim.x + threadIdx.x) * 4;
    if (i >= n) return;
    float4 v = *(const float4*)(src + i);
    uint32_t h0, h1, l0, l1;
    split_pack(v.x, v.y, h0, l0);
    split_pack(v.z, v.w, h1, l1);
    *(uint2*)(dh + i) = make_uint2(h0, h1);
    *(uint2*)(dl + i) = make_uint2(l0, l1);
}

// ---------------------------------------------------------------------------
// Split-bf16 HMMA GEMM, cp.async double-buffered.
// CTA 128x128, BK=32, 8 warps (2x4). Tiles pre-split in global bf16.
// Smem layout per tile: 2 m-rows per 128B line, chunk swizzle (validated r3).
// ---------------------------------------------------------------------------

__device__ __forceinline__ uint32_t tile_off(int r, int c) {
    return (uint32_t)((r >> 1) * 128 + (((((r & 1) << 2) | c) ^ ((r >> 1) & 7)) << 4));
}

#define GEMM_SMEM_BYTES (2 * 32768)

__global__ __launch_bounds__(256, 1) void gemm_bf16(float* __restrict__ Cout,
                                                    int qkv_mode)
{
    extern __shared__ char sm[];
    const uint32_t sb = smem_u32(sm);
    const int tid = threadIdx.x;
    const int lane = tid & 31;
    const int wid = tid >> 5;
    const int warp_m = wid >> 2;
    const int warp_n = wid & 3;
    const int z = blockIdx.z;

    const __nv_bfloat16 *Ah, *Al, *Bh, *Bl;
    if (qkv_mode) {
        Ah = g_Xh; Al = g_Xl;
        Bh = (z == 0) ? g_Wqh : (z == 1 ? g_Wkh : g_Wvh);
        Bl = (z == 0) ? g_Wql : (z == 1 ? g_Wkl : g_Wvl);
    } else {
        Ah = g_Oh; Al = g_Ol; Bh = g_Woh; Bl = g_Wol;
    }
    const int m0 = blockIdx.y * 128;
    const int n0 = blockIdx.x * 128;
    const __nv_bfloat16* Agh = Ah + (size_t)m0 * DMODEL;
    const __nv_bfloat16* Agl = Al + (size_t)m0 * DMODEL;
    const __nv_bfloat16* Bgh = Bh + (size_t)n0 * DMODEL;
    const __nv_bfloat16* Bgl = Bl + (size_t)n0 * DMODEL;

    // cp.async chunk assignment: 512 chunks/tile, 2 per thread per tile.
    const int l0r = tid >> 2, l0c = tid & 3;
    const int l1r = (256 + tid) >> 2, l1c = tid & 3;
    const uint32_t o0 = tile_off(l0r, l0c);
    const uint32_t o1 = tile_off(l1r, l1c);

    float acc[4][4][4];
#pragma unroll
    for (int i = 0; i < 4; i++)
#pragma unroll
        for (int j = 0; j < 4; j++)
#pragma unroll
            for (int u = 0; u < 4; u++) acc[i][j][u] = 0.f;

    const int a_mat = lane >> 3;
    const int a_khalf = a_mat >> 1;
    int rowA[4];
#pragma unroll
    for (int im = 0; im < 4; im++)
        rowA[im] = warp_m * 64 + im * 16 + (a_mat & 1) * 8 + (lane & 7);
    const int b_mat = (lane >> 3) & 1;
    const int b_ri = lane & 7;
    int rowB[4];
#pragma unroll
    for (int in = 0; in < 4; in++)
        rowB[in] = warp_n * 32 + in * 8 + b_ri;

#define ISSUE(chv)                                                              \
    do {                                                                        \
        const int _k0 = (chv) * 32;                                             \
        const uint32_t _bs = sb + (((chv) & 1) ? 32768u : 0u);                  \
        cp16(_bs + o0,         Agh + (size_t)l0r * DMODEL + _k0 + l0c * 8);     \
        cp16(_bs + o1,         Agh + (size_t)l1r * DMODEL + _k0 + l1c * 8);     \
        cp16(_bs + 8192 + o0,  Agl + (size_t)l0r * DMODEL + _k0 + l0c * 8);     \
        cp16(_bs + 8192 + o1,  Agl + (size_t)l1r * DMODEL + _k0 + l1c * 8);     \
        cp16(_bs + 16384 + o0, Bgh + (size_t)l0r * DMODEL + _k0 + l0c * 8);     \
        cp16(_bs + 16384 + o1, Bgh + (size_t)l1r * DMODEL + _k0 + l1c * 8);     \
        cp16(_bs + 24576 + o0, Bgl + (size_t)l0r * DMODEL + _k0 + l0c * 8);     \
        cp16(_bs + 24576 + o1, Bgl + (size_t)l1r * DMODEL + _k0 + l1c * 8);     \
        asm volatile("cp.async.commit_group;" ::: "memory");                    \
    } while (0)

    ISSUE(0);

    for (int ch = 0; ch < 32; ch++) {
        if (ch + 1 < 32) {
            ISSUE(ch + 1);
            asm volatile("cp.async.wait_group 1;" ::: "memory");
        } else {
            asm volatile("cp.async.wait_group 0;" ::: "memory");
        }
        __syncthreads();

        const uint32_t bs = sb + ((ch & 1) ? 32768u : 0u);
        const uint32_t sAh = bs, sAl = bs + 8192;
        const uint32_t sBh = bs + 16384, sBl = bs + 24576;
#pragma unroll
        for (int kk = 0; kk < 2; kk++) {
            uint32_t ah[4][4], al[4][4];
#pragma unroll
            for (int im = 0; im < 4; im++) {
                uint32_t off = tile_off(rowA[im], kk * 2 + a_khalf);
                ldsm_x4(ah[im], sAh + off);
                ldsm_x4(al[im], sAl + off);
            }
            uint32_t bh[4][2], bl[4][2];
#pragma unroll
            for (int in = 0; in < 4; in++) {
                uint32_t off = tile_off(rowB[in], kk * 2 + b_mat);
                ldsm_x2(bh[in], sBh + off);
                ldsm_x2(bl[in], sBl + off);
            }
#pragma unroll
            for (int im = 0; im < 4; im++)
#pragma unroll
                for (int in = 0; in < 4; in++) {
                    mma16816(acc[im][in], ah[im], bh[in]);
                    mma16816(acc[im][in], ah[im], bl[in]);
                    mma16816(acc[im][in], al[im], bh[in]);
                }
        }
        __syncthreads();
    }
#undef ISSUE

    const int gid = lane >> 2;
    const int tig = lane & 3;
    if (qkv_mode) {
        __nv_bfloat16 *Ch, *Cl;
        if (z == 0)      { Ch = g_Qh; Cl = g_Ql; }
        else if (z == 1) { Ch = g_Kh; Cl = g_Kl; }
        else             { Ch = g_Vh; Cl = g_Vl; }
        const float scale = (z == 0) ? 0.125f : 1.0f;   // Q pre-scaled
#pragma unroll
        for (int im = 0; im < 4; im++) {
#pragma unroll
            for (int in = 0; in < 4; in++) {
                int row = m0 + warp_m * 64 + im * 16 + gid;
                int col = n0 + warp_n * 32 + in * 8 + tig * 2;
                int h = col >> 6, hd = col & 63;
#pragma unroll
                for (int half = 0; half < 2; half++) {
                    int rr = row + half * 8;
                    int bb = rr >> 11, s = rr & 2047;
                    size_t off = (((size_t)(bb * NHEADS + h) * SEQ + s) << 6) + hd;
                    uint32_t hh, ll;
                    split_pack(acc[im][in][half * 2] * scale,
                               acc[im][in][half * 2 + 1] * scale, hh, ll);
                    *(uint32_t*)(Ch + off) = hh;
                    *(uint32_t*)(Cl + off) = ll;
                }
            }
        }
    } else {
#pragma unroll
        for (int im = 0; im < 4; im++) {
#pragma unroll
            for (int in = 0; in < 4; in++) {
                int row = m0 + warp_m * 64 + im * 16 + gid;
                int col = n0 + warp_n * 32 + in * 8 + tig * 2;
#pragma unroll
                for (int half = 0; half < 2; half++) {
                    int rr = row + half * 8;
                    float* dst = Cout + (size_t)rr * DMODEL + col;
                    dst[0] = acc[im][in][half * 2 + 0];
                    dst[1] = acc[im][in][half * 2 + 1];
                }
            }
        }
    }
}

// ---------------------------------------------------------------------------
// Flash attention (causal), split-bf16 HMMA. Br=Bc=64, Hd=64, 4 warps.
// Inputs already split-bf16 (Q pre-scaled). Fills are pure copies.
// ---------------------------------------------------------------------------

__device__ __forceinline__ uint32_t fl_off(int r, int c) {
    return (uint32_t)(r * 128 + ((c ^ (r & 7)) << 4));
}

__global__ __launch_bounds__(128) void flash_mma()
{
    __shared__ __align__(16) char sQh[8192];
    __shared__ __align__(16) char sQl[8192];
    __shared__ __align__(16) char sKh[8192];
    __shared__ __align__(16) char sKl[8192];
    __shared__ __align__(16) char sVh[8192];   // Vt hi: [d][s]
    __shared__ __align__(16) char sVl[8192];   // Vt lo

    const int tid = threadIdx.x;
    const int lane = tid & 31;
    const int wq = tid >> 5;
    const int qt = blockIdx.x;
    const int bh = blockIdx.y;
    const int q0 = qt * 64;

    const __nv_bfloat16* qbh = g_Qh + (size_t)(bh * SEQ + q0) * 64;
    const __nv_bfloat16* qbl = g_Ql + (size_t)(bh * SEQ + q0) * 64;
    const __nv_bfloat16* kbh = g_Kh + (size_t)bh * SEQ * 64;
    const __nv_bfloat16* kbl = g_Kl + (size_t)bh * SEQ * 64;
    const __nv_bfloat16* vbh = g_Vh + (size_t)bh * SEQ * 64;
    const __nv_bfloat16* vbl = g_Vl + (size_t)bh * SEQ * 64;

    const uint32_t aQh = smem_u32(sQh), aQl = smem_u32(sQl);
    const uint32_t aKh = smem_u32(sKh), aKl = smem_u32(sKl);
    const uint32_t aVh = smem_u32(sVh), aVl = smem_u32(sVl);

    // ---- Fill Q: straight 16B copies into swizzled tile ----
#pragma unroll
    for (int u = 0; u < 4; u++) {
        int lin = u * 128 + tid;
        int r = lin >> 3, c = lin & 7;
        uint32_t off = fl_off(r, c);
        *(uint4*)(sQh + off) = *(const uint4*)(qbh + r * 64 + c * 8);
        *(uint4*)(sQl + off) = *(const uint4*)(qbl + r * 64 + c * 8);
    }

    const int a_mat = lane >> 3;
    const int a_khalf = a_mat >> 1;
    const int rowA = wq * 16 + (a_mat & 1) * 8 + (lane & 7);
    const int b_mat = (lane >> 3) & 1;
    const int b_ri = lane & 7;
    const int gid = lane >> 2;
    const int tig = lane & 3;

    float m[2], l[2], o[8][4], s[8][4];
#pragma unroll
    for (int i = 0; i < 2; i++) { m[i] = neg_inf(); l[i] = 0.f; }
#pragma unroll
    for (int j = 0; j < 8; j++)
#pragma unroll
        for (int u = 0; u < 4; u++) o[j][u] = 0.f;

    // V transpose lane roles
    const int sp = tid & 31;
    const int dg = tid >> 5;

    for (int t = 0; t <= qt; t++) {
        __syncthreads();
        // ---- Fill K: 16B copies ----
#pragma unroll
        for (int u = 0; u < 4; u++) {
            int lin = u * 128 + tid;
            int r = lin >> 3, c = lin & 7;
            uint32_t off = fl_off(r, c);
            const size_t g = (size_t)(t * 64 + r) * 64 + c * 8;
            *(uint4*)(sKh + off) = *(const uint4*)(kbh + g);
            *(uint4*)(sKl + off) = *(const uint4*)(kbl + g);
        }
        // ---- Fill Vt [d][s]: register half-word transpose of (2sp, 2sp+1) ----
        {
            const size_t g0 = (size_t)(t * 64 + 2 * sp) * 64 + dg * 16;
#pragma unroll
            for (int arr = 0; arr < 2; arr++) {
                const __nv_bfloat16* vb = arr ? vbl : vbh;
                char* sv = arr ? sVl : sVh;
                uint4 a0 = *(const uint4*)(vb + g0);
                uint4 a1 = *(const uint4*)(vb + g0 + 8);
                uint4 b0 = *(const uint4*)(vb + g0 + 64);
                uint4 b1 = *(const uint4*)(vb + g0 + 72);
                uint32_t wa[8] = {a0.x, a0.y, a0.z, a0.w, a1.x, a1.y, a1.z, a1.w};
                uint32_t wb[8] = {b0.x, b0.y, b0.z, b0.w, b1.x, b1.y, b1.z, b1.w};
#pragma unroll
                for (int j = 0; j < 8; j++) {
                    int d0 = dg * 16 + 2 * j;
                    uint32_t out0 = (wa[j] & 0xffffu) | (wb[j] << 16);
                    uint32_t out1 = (wa[j] >> 16) | (wb[j] & 0xffff0000u);
                    uint32_t ad0 = d0 * 128 + ((((sp >> 2) ^ (d0 & 7))) << 4) + ((sp & 3) * 4);
                    int d1 = d0 + 1;
                    uint32_t ad1 = d1 * 128 + ((((sp >> 2) ^ (d1 & 7))) << 4) + ((sp & 3) * 4);
                    *(uint32_t*)(sv + ad0) = out0;
                    *(uint32_t*)(sv + ad1) = out1;
                }
            }
        }
        __syncthreads();

        // ---- S = Q K^T ----
#pragma unroll
        for (int j = 0; j < 8; j++)
#pragma unroll
            for (int u = 0; u < 4; u++) s[j][u] = 0.f;

#pragma unroll
        for (int kk = 0; kk < 4; kk++) {
            uint32_t ah[4], al[4];
            uint32_t offa = fl_off(rowA, kk * 2 + a_khalf);
            ldsm_x4(ah, aQh + offa);
            ldsm_x4(al, aQl + offa);
#pragma unroll
            for (int j = 0; j < 8; j++) {
                uint32_t bhf[2], blf[2];
                uint32_t offb = fl_off(j * 8 + b_ri, kk * 2 + b_mat);
                ldsm_x2(bhf, aKh + offb);
                ldsm_x2(blf, aKl + offb);
                mma16816(s[j], ah, bhf);
                mma16816(s[j], ah, blf);
                mma16816(s[j], al, bhf);
            }
        }

        if (t == qt) {
#pragma unroll
            for (int j = 0; j < 8; j++) {
#pragma unroll
                for (int u = 0; u < 4; u++) {
                    int row = wq * 16 + (u >> 1) * 8 + gid;
                    int col = j * 8 + tig * 2 + (u & 1);
                    if (col > row) s[j][u] = neg_inf();
                }
            }
        }

        // ---- Online softmax ----
#pragma unroll
        for (int i = 0; i < 2; i++) {
            float mx = neg_inf();
#pragma unroll
            for (int j = 0; j < 8; j++) {
                mx = fmaxf(mx, s[j][i * 2]);
                mx = fmaxf(mx, s[j][i * 2 + 1]);
            }
            mx = fmaxf(mx, __shfl_xor_sync(0xffffffffu, mx, 1));
            mx = fmaxf(mx, __shfl_xor_sync(0xffffffffu, mx, 2));
            float mnew = fmaxf(m[i], mx);
            float corr = __expf(m[i] - mnew);
            float rs = 0.f;
#pragma unroll
            for (int j = 0; j < 8; j++) {
                float e0 = __expf(s[j][i * 2] - mnew);
                float e1 = __expf(s[j][i * 2 + 1] - mnew);
                s[j][i * 2] = e0;
                s[j][i * 2 + 1] = e1;
                rs += e0 + e1;
            }
            rs += __shfl_xor_sync(0xffffffffu, rs, 1);
            rs += __shfl_xor_sync(0xffffffffu, rs, 2);
            l[i] = l[i] * corr + rs;
            m[i] = mnew;
#pragma unroll
            for (int j = 0; j < 8; j++) {
                o[j][i * 2] *= corr;
                o[j][i * 2 + 1] *= corr;
            }
        }

        // ---- O += P Vt ----
#pragma unroll
        for (int kk = 0; kk < 4; kk++) {
            uint32_t ph[4], pl[4];
#pragma unroll
            for (int half = 0; half < 2; half++) {
                const float* sv = s[2 * kk + half];
                split_pack(sv[0], sv[1], ph[half * 2], pl[half * 2]);
                split_pack(sv[2], sv[3], ph[half * 2 + 1], pl[half * 2 + 1]);
            }
#pragma unroll
            for (int j = 0; j < 8; j++) {
                uint32_t vhf[2], vlf[2];
                uint32_t offv = fl_off(j * 8 + b_ri, kk * 2 + b_mat);
                ldsm_x2(vhf, aVh + offv);
                ldsm_x2(vlf, aVl + offv);
                mma16816(o[j], ph, vhf);
                mma16816(o[j], ph, vlf);
                mma16816(o[j], pl, vhf);
            }
        }
    }

    // ---- Epilogue: normalize, write split-bf16 O [token][dmodel] ----
    const int bb = bh >> 4;
    const int h = bh & 15;
    float inv0 = 1.f / l[0];
    float inv1 = 1.f / l[1];
#pragma unroll
    for (int j = 0; j < 8; j++) {
        int col = h * 64 + j * 8 + tig * 2;
        int r0 = q0 + wq * 16 + gid;
        size_t off0 = (size_t)(bb * SEQ + r0) * DMODEL + col;
        size_t off1 = (size_t)(bb * SEQ + r0 + 8) * DMODEL + col;
        uint32_t hh, ll;
        split_pack(o[j][0] * inv0, o[j][1] * inv0, hh, ll);
        *(uint32_t*)(g_Oh + off0) = hh;
        *(uint32_t*)(g_Ol + off0) = ll;
        split_pack(o[j][2] * inv1, o[j][3] * inv1, hh, ll);
        *(uint32_t*)(g_Oh + off1) = hh;
        *(uint32_t*)(g_Ol + off1) = ll;
    }
}

// ---------------------------------------------------------------------------

extern "C" void kernel_launch(void* const* d_in, const int* in_sizes, int n_in,
                              void* d_out, int out_size)
{
    (void)in_sizes; (void)n_in; (void)out_size;
    const float* x  = (const float*)d_in[0];
    const float* Wq = (const float*)d_in[1];
    const float* Wk = (const float*)d_in[2];
    const float* Wv = (const float*)d_in[3];
    const float* Wo = (const float*)d_in[4];
    float* out = (float*)d_out;

    // Idempotent, not a stream op (not captured); called unconditionally —
    // no static guards allowed in kernel_launch.
    cudaFuncSetAttribute(gemm_bf16, cudaFuncAttributeMaxDynamicSharedMemorySize,
                         GEMM_SMEM_BYTES);

    convert_split<<<dim3(4096, 5), 256>>>(x, Wq, Wk, Wv, Wo);

    dim3 gqkv(DMODEL / 128, TOKENS / 128, 3);
    gemm_bf16<<<gqkv, 256, GEMM_SMEM_BYTES>>>(nullptr, 1);

    dim3 gatt(SEQ / 64, 2 * NHEADS);
    flash_mma<<<gatt, 128>>>();

    dim3 gout(DMODEL / 128, TOKENS / 128, 1);
    gemm_bf16<<<gout, 256, GEMM_SMEM_BYTES>>>(out, 0);
}

// round 8
// speedup vs baseline: 3.7849x; 1.2417x over previous
#include <cuda_runtime.h>
#include <cuda_bf16.h>
#include <cstdint>

#define TOKENS 4096
#define DMODEL 1024
#define NHEADS 16
#define SEQ 2048

// Persistent split-bf16 copies (hi/lo).
__device__ __align__(16) __nv_bfloat16 g_Xh[TOKENS * DMODEL];
__device__ __align__(16) __nv_bfloat16 g_Xl[TOKENS * DMODEL];
__device__ __align__(16) __nv_bfloat16 g_Wqh[DMODEL * DMODEL];
__device__ __align__(16) __nv_bfloat16 g_Wql[DMODEL * DMODEL];
__device__ __align__(16) __nv_bfloat16 g_Wkh[DMODEL * DMODEL];
__device__ __align__(16) __nv_bfloat16 g_Wkl[DMODEL * DMODEL];
__device__ __align__(16) __nv_bfloat16 g_Wvh[DMODEL * DMODEL];
__device__ __align__(16) __nv_bfloat16 g_Wvl[DMODEL * DMODEL];
__device__ __align__(16) __nv_bfloat16 g_Woh[DMODEL * DMODEL];
__device__ __align__(16) __nv_bfloat16 g_Wol[DMODEL * DMODEL];
// Q (pre-scaled) and K: [B*H][S][64]. V: TRANSPOSED [B*H][64][S]. O: [token][dmodel].
__device__ __align__(16) __nv_bfloat16 g_Qh[TOKENS * DMODEL];
__device__ __align__(16) __nv_bfloat16 g_Ql[TOKENS * DMODEL];
__device__ __align__(16) __nv_bfloat16 g_Kh[TOKENS * DMODEL];
__device__ __align__(16) __nv_bfloat16 g_Kl[TOKENS * DMODEL];
__device__ __align__(16) __nv_bfloat16 g_Vh[TOKENS * DMODEL];
__device__ __align__(16) __nv_bfloat16 g_Vl[TOKENS * DMODEL];
__device__ __align__(16) __nv_bfloat16 g_Oh[TOKENS * DMODEL];
__device__ __align__(16) __nv_bfloat16 g_Ol[TOKENS * DMODEL];

__device__ __forceinline__ float neg_inf() { return __int_as_float(0xff800000u); }

__device__ __forceinline__ uint32_t smem_u32(const void* p) {
    uint32_t a;
    asm("{ .reg .u64 t; cvta.to.shared.u64 t, %1; cvt.u32.u64 %0, t; }"
        : "=r"(a) : "l"(p));
    return a;
}

__device__ __forceinline__ uint32_t pack_bf2(__nv_bfloat16 a, __nv_bfloat16 b) {
    return (uint32_t)__bfloat16_as_ushort(a) |
           ((uint32_t)__bfloat16_as_ushort(b) << 16);
}

__device__ __forceinline__ void split_pack(float a, float b,
                                           uint32_t& h, uint32_t& l) {
    __nv_bfloat16 ha = __float2bfloat16_rn(a);
    __nv_bfloat16 hb = __float2bfloat16_rn(b);
    __nv_bfloat16 la = __float2bfloat16_rn(a - __bfloat162float(ha));
    __nv_bfloat16 lb = __float2bfloat16_rn(b - __bfloat162float(hb));
    h = pack_bf2(ha, hb);
    l = pack_bf2(la, lb);
}

__device__ __forceinline__ void ldsm_x4(uint32_t* r, uint32_t addr) {
    asm volatile("ldmatrix.sync.aligned.m8n8.x4.shared.b16 {%0,%1,%2,%3}, [%4];"
                 : "=r"(r[0]), "=r"(r[1]), "=r"(r[2]), "=r"(r[3]) : "r"(addr));
}

__device__ __forceinline__ void mma16816(float* d, const uint32_t* a,
                                         const uint32_t* b) {
    asm volatile("mma.sync.aligned.m16n8k16.row.col.f32.bf16.bf16.f32 "
                 "{%0,%1,%2,%3}, {%4,%5,%6,%7}, {%8,%9}, {%0,%1,%2,%3};"
                 : "+f"(d[0]), "+f"(d[1]), "+f"(d[2]), "+f"(d[3])
                 : "r"(a[0]), "r"(a[1]), "r"(a[2]), "r"(a[3]),
                   "r"(b[0]), "r"(b[1]));
}

__device__ __forceinline__ void cp16(uint32_t saddr, const void* gaddr) {
    asm volatile("cp.async.cg.shared.global [%0], [%1], 16;"
                 :: "r"(saddr), "l"(gaddr));
}

// ---------------------------------------------------------------------------
// Pre-pass: split fp32 sources into bf16 hi/lo.
// ---------------------------------------------------------------------------

__global__ void convert_split(const float* __restrict__ x,
                              const float* __restrict__ Wq,
                              const float* __restrict__ Wk,
                              const float* __restrict__ Wv,
                              const float* __restrict__ Wo)
{
    const float* src;
    __nv_bfloat16 *dh, *dl;
    int n;
    switch (blockIdx.y) {
        case 0: src = x;  dh = g_Xh;  dl = g_Xl;  n = TOKENS * DMODEL; break;
        case 1: src = Wq; dh = g_Wqh; dl = g_Wql; n = DMODEL * DMODEL; break;
        case 2: src = Wk; dh = g_Wkh; dl = g_Wkl; n = DMODEL * DMODEL; break;
        case 3: src = Wv; dh = g_Wvh; dl = g_Wvl; n = DMODEL * DMODEL; break;
        default: src = Wo; dh = g_Woh; dl = g_Wol; n = DMODEL * DMODEL; break;
    }
    int i = (blockIdx.x * blockDim.x + threadIdx.x) * 4;
    if (i >= n) return;
    float4 v = *(const float4*)(src + i);
    uint32_t h0, h1, l0, l1;
    split_pack(v.x, v.y, h0, l0);
    split_pack(v.z, v.w, h1, l1);
    *(uint2*)(dh + i) = make_uint2(h0, h1);
    *(uint2*)(dl + i) = make_uint2(l0, l1);
}

// ---------------------------------------------------------------------------
// Split-bf16 HMMA GEMM, cp.async double-buffered, CTA 128x256, BK=32.
// 8 warps 2x4, warp tile 64x64 (4 im x 8 in). Paired-x4 B-frag loads.
// ---------------------------------------------------------------------------

__device__ __forceinline__ uint32_t tile_off(int r, int c) {
    return (uint32_t)((r >> 1) * 128 + (((((r & 1) << 2) | c) ^ ((r >> 1) & 7)) << 4));
}

#define G_STAGE 49152
#define GEMM_SMEM_BYTES (2 * G_STAGE)

__global__ __launch_bounds__(256, 1) void gemm_bf16(float* __restrict__ Cout,
                                                    int qkv_mode)
{
    extern __shared__ char sm[];
    const uint32_t sb = smem_u32(sm);
    const int tid = threadIdx.x;
    const int lane = tid & 31;
    const int wid = tid >> 5;
    const int warp_m = wid >> 2;
    const int warp_n = wid & 3;
    const int z = blockIdx.z;

    const __nv_bfloat16 *Ah, *Al, *Bh, *Bl;
    if (qkv_mode) {
        Ah = g_Xh; Al = g_Xl;
        Bh = (z == 0) ? g_Wqh : (z == 1 ? g_Wkh : g_Wvh);
        Bl = (z == 0) ? g_Wql : (z == 1 ? g_Wkl : g_Wvl);
    } else {
        Ah = g_Oh; Al = g_Ol; Bh = g_Woh; Bl = g_Wol;
    }
    const int m0 = blockIdx.y * 128;
    const int n0 = blockIdx.x * 256;
    const __nv_bfloat16* Agh = Ah + (size_t)m0 * DMODEL;
    const __nv_bfloat16* Agl = Al + (size_t)m0 * DMODEL;
    const __nv_bfloat16* Bgh = Bh + (size_t)n0 * DMODEL;
    const __nv_bfloat16* Bgl = Bl + (size_t)n0 * DMODEL;

    // cp.async assignment: A 512 chunks (2/thread), B 1024 chunks (4/thread).
    const int cA = tid & 3;
    int rA[2]; uint32_t oA[2];
#pragma unroll
    for (int u = 0; u < 2; u++) { rA[u] = (u * 256 + tid) >> 2; oA[u] = tile_off(rA[u], cA); }
    int rB[4]; uint32_t oB[4];
#pragma unroll
    for (int u = 0; u < 4; u++) { rB[u] = (u * 256 + tid) >> 2; oB[u] = tile_off(rB[u], cA); }

    float acc[4][8][4];
#pragma unroll
    for (int i = 0; i < 4; i++)
#pragma unroll
        for (int j = 0; j < 8; j++)
#pragma unroll
            for (int u = 0; u < 4; u++) acc[i][j][u] = 0.f;

    // A-frag addressing (validated mapping)
    const int a_mat = lane >> 3;
    const int a_khalf = a_mat >> 1;
    int rowA[4];
#pragma unroll
    for (int im = 0; im < 4; im++)
        rowA[im] = warp_m * 64 + im * 16 + (a_mat & 1) * 8 + (lane & 7);
    // Paired B x4: mats {0,1} = n-tile j (khalf 0/1), mats {2,3} = n-tile j+1.
    const int b_row4 = ((lane >> 4) << 3) + (lane & 7);
    const int b_chunk4 = (lane >> 3) & 1;

#define ISSUE(chv)                                                                 \
    do {                                                                           \
        const int _k0 = (chv) * 32;                                                \
        const uint32_t _bs = sb + (((chv) & 1) ? (uint32_t)G_STAGE : 0u);          \
        cp16(_bs + oA[0],         Agh + (size_t)rA[0] * DMODEL + _k0 + cA * 8);    \
        cp16(_bs + oA[1],         Agh + (size_t)rA[1] * DMODEL + _k0 + cA * 8);    \
        cp16(_bs + 8192 + oA[0],  Agl + (size_t)rA[0] * DMODEL + _k0 + cA * 8);    \
        cp16(_bs + 8192 + oA[1],  Agl + (size_t)rA[1] * DMODEL + _k0 + cA * 8);    \
        cp16(_bs + 16384 + oB[0], Bgh + (size_t)rB[0] * DMODEL + _k0 + cA * 8);    \
        cp16(_bs + 16384 + oB[1], Bgh + (size_t)rB[1] * DMODEL + _k0 + cA * 8);    \
        cp16(_bs + 16384 + oB[2], Bgh + (size_t)rB[2] * DMODEL + _k0 + cA * 8);    \
        cp16(_bs + 16384 + oB[3], Bgh + (size_t)rB[3] * DMODEL + _k0 + cA * 8);    \
        cp16(_bs + 32768 + oB[0], Bgl + (size_t)rB[0] * DMODEL + _k0 + cA * 8);    \
        cp16(_bs + 32768 + oB[1], Bgl + (size_t)rB[1] * DMODEL + _k0 + cA * 8);    \
        cp16(_bs + 32768 + oB[2], Bgl + (size_t)rB[2] * DMODEL + _k0 + cA * 8);    \
        cp16(_bs + 32768 + oB[3], Bgl + (size_t)rB[3] * DMODEL + _k0 + cA * 8);    \
        asm volatile("cp.async.commit_group;" ::: "memory");                       \
    } while (0)

    ISSUE(0);

    for (int ch = 0; ch < 32; ch++) {
        asm volatile("cp.async.wait_group 0;" ::: "memory");
        __syncthreads();
        if (ch + 1 < 32) ISSUE(ch + 1);

        const uint32_t bs = sb + ((ch & 1) ? (uint32_t)G_STAGE : 0u);
        const uint32_t sAh = bs, sAl = bs + 8192;
        const uint32_t sBh = bs + 16384, sBl = bs + 32768;
#pragma unroll
        for (int kk = 0; kk < 2; kk++) {
            uint32_t ah[4][4], al[4][4];
#pragma unroll
            for (int im = 0; im < 4; im++) {
                uint32_t off = tile_off(rowA[im], kk * 2 + a_khalf);
                ldsm_x4(ah[im], sAh + off);
                ldsm_x4(al[im], sAl + off);
            }
#pragma unroll
            for (int inp = 0; inp < 4; inp++) {
                uint32_t bh4[4], bl4[4];
                uint32_t off = tile_off(warp_n * 64 + inp * 16 + b_row4,
                                        kk * 2 + b_chunk4);
                ldsm_x4(bh4, sBh + off);
                ldsm_x4(bl4, sBl + off);
#pragma unroll
                for (int im = 0; im < 4; im++) {
                    mma16816(acc[im][2 * inp], ah[im], bh4);
                    mma16816(acc[im][2 * inp], ah[im], bl4);
                    mma16816(acc[im][2 * inp], al[im], bh4);
                    mma16816(acc[im][2 * inp + 1], ah[im], bh4 + 2);
                    mma16816(acc[im][2 * inp + 1], ah[im], bl4 + 2);
                    mma16816(acc[im][2 * inp + 1], al[im], bh4 + 2);
                }
            }
        }
        __syncthreads();
    }
#undef ISSUE

    const int gid = lane >> 2;
    const int tig = lane & 3;
    if (qkv_mode) {
        if (z < 2) {
            __nv_bfloat16* Ch = (z == 0) ? g_Qh : g_Kh;
            __nv_bfloat16* Cl = (z == 0) ? g_Ql : g_Kl;
            const float scale = (z == 0) ? 0.125f : 1.0f;
#pragma unroll
            for (int im = 0; im < 4; im++) {
#pragma unroll
                for (int in = 0; in < 8; in++) {
                    int row = m0 + warp_m * 64 + im * 16 + gid;
                    int col = n0 + warp_n * 64 + in * 8 + tig * 2;
                    int h = col >> 6, hd = col & 63;
#pragma unroll
                    for (int half = 0; half < 2; half++) {
                        int rr = row + half * 8;
                        int bb = rr >> 11, s = rr & 2047;
                        size_t off = (((size_t)(bb * NHEADS + h) * SEQ + s) << 6) + hd;
                        uint32_t hh, ll;
                        split_pack(acc[im][in][half * 2] * scale,
                                   acc[im][in][half * 2 + 1] * scale, hh, ll);
                        *(uint32_t*)(Ch + off) = hh;
                        *(uint32_t*)(Cl + off) = ll;
                    }
                }
            }
        } else {
            // V: write TRANSPOSED [bh][d][s] (scalar bf16 stores).
#pragma unroll
            for (int im = 0; im < 4; im++) {
#pragma unroll
                for (int in = 0; in < 8; in++) {
                    int row = m0 + warp_m * 64 + im * 16 + gid;
                    int col = n0 + warp_n * 64 + in * 8 + tig * 2;
                    int h = col >> 6, hd = col & 63;
#pragma unroll
                    for (int half = 0; half < 2; half++) {
                        int rr = row + half * 8;
                        int bb = rr >> 11, s = rr & 2047;
                        size_t base = ((size_t)(bb * NHEADS + h) * 64 + hd) * SEQ + s;
#pragma unroll
                        for (int e = 0; e < 2; e++) {
                            float v = acc[im][in][half * 2 + e];
                            __nv_bfloat16 hb = __float2bfloat16_rn(v);
                            __nv_bfloat16 lb =
                                __float2bfloat16_rn(v - __bfloat162float(hb));
                            g_Vh[base + (size_t)e * SEQ] = hb;
                            g_Vl[base + (size_t)e * SEQ] = lb;
                        }
                    }
                }
            }
        }
    } else {
#pragma unroll
        for (int im = 0; im < 4; im++) {
#pragma unroll
            for (int in = 0; in < 8; in++) {
                int row = m0 + warp_m * 64 + im * 16 + gid;
                int col = n0 + warp_n * 64 + in * 8 + tig * 2;
#pragma unroll
                for (int half = 0; half < 2; half++) {
                    int rr = row + half * 8;
                    float* dst = Cout + (size_t)rr * DMODEL + col;
                    dst[0] = acc[im][in][half * 2 + 0];
                    dst[1] = acc[im][in][half * 2 + 1];
                }
            }
        }
    }
}

// ---------------------------------------------------------------------------
// Flash attention (causal), split-bf16 HMMA. Br=128, Bc=64, 8 warps.
// K tiles and Vt tiles ([d][s], pre-transposed) double-buffered via cp.async.
// Smem: Q 32KB | stage0 {Kh,Kl,Vh,Vl} 32KB | stage1 32KB  = 96KB dynamic.
// ---------------------------------------------------------------------------

__device__ __forceinline__ uint32_t fl_off(int r, int c) {
    return (uint32_t)(r * 128 + ((c ^ (r & 7)) << 4));
}

#define F_SMEM_BYTES (32768 + 2 * 32768)

__global__ __launch_bounds__(256, 1) void flash_mma()
{
    extern __shared__ char sm[];
    const uint32_t sb = smem_u32(sm);
    const int tid = threadIdx.x;
    const int lane = tid & 31;
    const int wq = tid >> 5;       // 0..7: q-rows wq*16..+15
    const int qt = blockIdx.x;     // 0..15 (128-row q tiles)
    const int bh = blockIdx.y;
    const int q0 = qt * 128;
    const int T = 2 * qt + 2;      // number of 64-col k tiles

    const __nv_bfloat16* qbh = g_Qh + (size_t)(bh * SEQ + q0) * 64;
    const __nv_bfloat16* qbl = g_Ql + (size_t)(bh * SEQ + q0) * 64;
    const __nv_bfloat16* kbh = g_Kh + (size_t)bh * SEQ * 64;
    const __nv_bfloat16* kbl = g_Kl + (size_t)bh * SEQ * 64;
    const __nv_bfloat16* vth = g_Vh + (size_t)bh * 64 * SEQ;   // [d][s]
    const __nv_bfloat16* vtl = g_Vl + (size_t)bh * 64 * SEQ;

    const uint32_t aQh = sb, aQl = sb + 16384;

    // ---- Fill Q (plain 16B copies): 128 rows x 8 chunks, 4/thread ----
#pragma unroll
    for (int u = 0; u < 4; u++) {
        int lin = u * 256 + tid;
        int r = lin >> 3, c = lin & 7;
        uint32_t off = fl_off(r, c);
        *(uint4*)(sm + off)         = *(const uint4*)(qbh + r * 64 + c * 8);
        *(uint4*)(sm + 16384 + off) = *(const uint4*)(qbl + r * 64 + c * 8);
    }

    // K/V cp.async assignment: 512 chunks each array, 2/thread.
    int rF[2]; uint32_t oF[2];
#pragma unroll
    for (int u = 0; u < 2; u++) {
        int lin = u * 256 + tid;
        rF[u] = lin >> 3;
        oF[u] = fl_off(rF[u], lin & 7);
    }
    const int cF0 = (tid & 7) * 8, cF1 = ((256 + tid) & 7) * 8;

#define F_ISSUE(tt)                                                                 \
    do {                                                                            \
        const uint32_t _bs = sb + 32768u + (((tt) & 1) ? 32768u : 0u);              \
        cp16(_bs + oF[0],         kbh + (size_t)((tt) * 64 + rF[0]) * 64 + cF0);    \
        cp16(_bs + oF[1],         kbh + (size_t)((tt) * 64 + rF[1]) * 64 + cF1);    \
        cp16(_bs + 8192 + oF[0],  kbl + (size_t)((tt) * 64 + rF[0]) * 64 + cF0);    \
        cp16(_bs + 8192 + oF[1],  kbl + (size_t)((tt) * 64 + rF[1]) * 64 + cF1);    \
        cp16(_bs + 16384 + oF[0], vth + (size_t)rF[0] * SEQ + (tt) * 64 + cF0);     \
        cp16(_bs + 16384 + oF[1], vth + (size_t)rF[1] * SEQ + (tt) * 64 + cF1);     \
        cp16(_bs + 24576 + oF[0], vtl + (size_t)rF[0] * SEQ + (tt) * 64 + cF0);     \
        cp16(_bs + 24576 + oF[1], vtl + (size_t)rF[1] * SEQ + (tt) * 64 + cF1);     \
        asm volatile("cp.async.commit_group;" ::: "memory");                        \
    } while (0)

    F_ISSUE(0);

    const int a_mat = lane >> 3;
    const int a_khalf = a_mat >> 1;
    const int rowA = wq * 16 + (a_mat & 1) * 8 + (lane & 7);
    const int b_row4 = ((lane >> 4) << 3) + (lane & 7);
    const int b_chunk4 = (lane >> 3) & 1;
    const int gid = lane >> 2;
    const int tig = lane & 3;

    float m[2], l[2], o[8][4], s[8][4];
#pragma unroll
    for (int i = 0; i < 2; i++) { m[i] = neg_inf(); l[i] = 0.f; }
#pragma unroll
    for (int j = 0; j < 8; j++)
#pragma unroll
        for (int u = 0; u < 4; u++) o[j][u] = 0.f;

    for (int t = 0; t < T; t++) {
        asm volatile("cp.async.wait_group 0;" ::: "memory");
        __syncthreads();
        if (t + 1 < T) F_ISSUE(t + 1);

        const uint32_t bs = sb + 32768u + ((t & 1) ? 32768u : 0u);
        const uint32_t aKh = bs, aKl = bs + 8192;
        const uint32_t aVh = bs + 16384, aVl = bs + 24576;

        // ---- S = Q K^T ----
#pragma unroll
        for (int j = 0; j < 8; j++)
#pragma unroll
            for (int u = 0; u < 4; u++) s[j][u] = 0.f;

#pragma unroll
        for (int kk = 0; kk < 4; kk++) {
            uint32_t ah[4], al[4];
            uint32_t offa = fl_off(rowA, kk * 2 + a_khalf);
            ldsm_x4(ah, aQh + offa);
            ldsm_x4(al, aQl + offa);
#pragma unroll
            for (int jp = 0; jp < 4; jp++) {
                uint32_t bh4[4], bl4[4];
                uint32_t offb = fl_off(jp * 16 + b_row4, kk * 2 + b_chunk4);
                ldsm_x4(bh4, aKh + offb);
                ldsm_x4(bl4, aKl + offb);
                mma16816(s[2 * jp], ah, bh4);
                mma16816(s[2 * jp], ah, bl4);
                mma16816(s[2 * jp], al, bh4);
                mma16816(s[2 * jp + 1], ah, bh4 + 2);
                mma16816(s[2 * jp + 1], ah, bl4 + 2);
                mma16816(s[2 * jp + 1], al, bh4 + 2);
            }
        }

        // ---- Causal mask (only tiles overlapping the diagonal) ----
        if (t >= 2 * qt) {
#pragma unroll
            for (int j = 0; j < 8; j++) {
#pragma unroll
                for (int u = 0; u < 4; u++) {
                    int row = q0 + wq * 16 + (u >> 1) * 8 + gid;
                    int col = t * 64 + j * 8 + tig * 2 + (u & 1);
                    if (col > row) s[j][u] = neg_inf();
                }
            }
        }

        // ---- Online softmax ----
#pragma unroll
        for (int i = 0; i < 2; i++) {
            float mx = neg_inf();
#pragma unroll
            for (int j = 0; j < 8; j++) {
                mx = fmaxf(mx, s[j][i * 2]);
                mx = fmaxf(mx, s[j][i * 2 + 1]);
            }
            mx = fmaxf(mx, __shfl_xor_sync(0xffffffffu, mx, 1));
            mx = fmaxf(mx, __shfl_xor_sync(0xffffffffu, mx, 2));
            float mnew = fmaxf(m[i], mx);
            float corr = __expf(m[i] - mnew);
            float rs = 0.f;
#pragma unroll
            for (int j = 0; j < 8; j++) {
                float e0 = __expf(s[j][i * 2] - mnew);
                float e1 = __expf(s[j][i * 2 + 1] - mnew);
                s[j][i * 2] = e0;
                s[j][i * 2 + 1] = e1;
                rs += e0 + e1;
            }
            rs += __shfl_xor_sync(0xffffffffu, rs, 1);
            rs += __shfl_xor_sync(0xffffffffu, rs, 2);
            l[i] = l[i] * corr + rs;
            m[i] = mnew;
#pragma unroll
            for (int j = 0; j < 8; j++) {
                o[j][i * 2] *= corr;
                o[j][i * 2 + 1] *= corr;
            }
        }

        // ---- O += P Vt ----
#pragma unroll
        for (int kk = 0; kk < 4; kk++) {
            uint32_t ph[4], pl[4];
#pragma unroll
            for (int half = 0; half < 2; half++) {
                const float* sv = s[2 * kk + half];
                split_pack(sv[0], sv[1], ph[half * 2], pl[half * 2]);
                split_pack(sv[2], sv[3], ph[half * 2 + 1], pl[half * 2 + 1]);
            }
#pragma unroll
            for (int jp = 0; jp < 4; jp++) {
                uint32_t vh4[4], vl4[4];
                uint32_t offv = fl_off(jp * 16 + b_row4, kk * 2 + b_chunk4);
                ldsm_x4(vh4, aVh + offv);
                ldsm_x4(vl4, aVl + offv);
                mma16816(o[2 * jp], ph, vh4);
                mma16816(o[2 * jp], ph, vl4);
                mma16816(o[2 * jp], pl, vh4);
                mma16816(o[2 * jp + 1], ph, vh4 + 2);
                mma16816(o[2 * jp + 1], ph, vl4 + 2);
                mma16816(o[2 * jp + 1], pl, vh4 + 2);
            }
        }
    }
#undef F_ISSUE

    // ---- Epilogue: normalize, write split-bf16 O [token][dmodel] ----
    const int bb = bh >> 4;
    const int h = bh & 15;
    float inv0 = 1.f / l[0];
    float inv1 = 1.f / l[1];
#pragma unroll
    for (int j = 0; j < 8; j++) {
        int col = h * 64 + j * 8 + tig * 2;
        int r0 = q0 + wq * 16 + gid;
        size_t off0 = (size_t)(bb * SEQ + r0) * DMODEL + col;
        size_t off1 = (size_t)(bb * SEQ + r0 + 8) * DMODEL + col;
        uint32_t hh, ll;
        split_pack(o[j][0] * inv0, o[j][1] * inv0, hh, ll);
        *(uint32_t*)(g_Oh + off0) = hh;
        *(uint32_t*)(g_Ol + off0) = ll;
        split_pack(o[j][2] * inv1, o[j][3] * inv1, hh, ll);
        *(uint32_t*)(g_Oh + off1) = hh;
        *(uint32_t*)(g_Ol + off1) = ll;
    }
}

// ---------------------------------------------------------------------------

extern "C" void kernel_launch(void* const* d_in, const int* in_sizes, int n_in,
                              void* d_out, int out_size)
{
    (void)in_sizes; (void)n_in; (void)out_size;
    const float* x  = (const float*)d_in[0];
    const float* Wq = (const float*)d_in[1];
    const float* Wk = (const float*)d_in[2];
    const float* Wv = (const float*)d_in[3];
    const float* Wo = (const float*)d_in[4];
    float* out = (float*)d_out;

    // Idempotent host-side attribute sets (not captured stream ops).
    cudaFuncSetAttribute(gemm_bf16, cudaFuncAttributeMaxDynamicSharedMemorySize,
                         GEMM_SMEM_BYTES);
    cudaFuncSetAttribute(flash_mma, cudaFuncAttributeMaxDynamicSharedMemorySize,
                         F_SMEM_BYTES);

    convert_split<<<dim3(4096, 5), 256>>>(x, Wq, Wk, Wv, Wo);

    dim3 gqkv(DMODEL / 256, TOKENS / 128, 3);   // (4, 32, 3)
    gemm_bf16<<<gqkv, 256, GEMM_SMEM_BYTES>>>(nullptr, 1);

    dim3 gatt(SEQ / 128, 2 * NHEADS);           // (16, 32)
    flash_mma<<<gatt, 256, F_SMEM_BYTES>>>();

    dim3 gout(DMODEL / 256, TOKENS / 128, 1);   // (4, 32)
    gemm_bf16<<<gout, 256, GEMM_SMEM_BYTES>>>(out, 0);
}

// round 9
// speedup vs baseline: 3.8026x; 1.0047x over previous
#include <cuda_runtime.h>
#include <cuda_bf16.h>
#include <cstdint>

#define TOKENS 4096
#define DMODEL 1024
#define NHEADS 16
#define SEQ 2048

// Persistent split-bf16 copies (hi/lo).
__device__ __align__(16) __nv_bfloat16 g_Xh[TOKENS * DMODEL];
__device__ __align__(16) __nv_bfloat16 g_Xl[TOKENS * DMODEL];
__device__ __align__(16) __nv_bfloat16 g_Wqh[DMODEL * DMODEL];
__device__ __align__(16) __nv_bfloat16 g_Wql[DMODEL * DMODEL];
__device__ __align__(16) __nv_bfloat16 g_Wkh[DMODEL * DMODEL];
__device__ __align__(16) __nv_bfloat16 g_Wkl[DMODEL * DMODEL];
__device__ __align__(16) __nv_bfloat16 g_Wvh[DMODEL * DMODEL];
__device__ __align__(16) __nv_bfloat16 g_Wvl[DMODEL * DMODEL];
__device__ __align__(16) __nv_bfloat16 g_Woh[DMODEL * DMODEL];
__device__ __align__(16) __nv_bfloat16 g_Wol[DMODEL * DMODEL];
// Q (pre-scaled) and K: [B*H][S][64]. V: TRANSPOSED [B*H][64][S]. O: [token][dmodel].
__device__ __align__(16) __nv_bfloat16 g_Qh[TOKENS * DMODEL];
__device__ __align__(16) __nv_bfloat16 g_Ql[TOKENS * DMODEL];
__device__ __align__(16) __nv_bfloat16 g_Kh[TOKENS * DMODEL];
__device__ __align__(16) __nv_bfloat16 g_Kl[TOKENS * DMODEL];
__device__ __align__(16) __nv_bfloat16 g_Vh[TOKENS * DMODEL];
__device__ __align__(16) __nv_bfloat16 g_Vl[TOKENS * DMODEL];
__device__ __align__(16) __nv_bfloat16 g_Oh[TOKENS * DMODEL];
__device__ __align__(16) __nv_bfloat16 g_Ol[TOKENS * DMODEL];

__device__ __forceinline__ float neg_inf() { return __int_as_float(0xff800000u); }

__device__ __forceinline__ uint32_t smem_u32(const void* p) {
    uint32_t a;
    asm("{ .reg .u64 t; cvta.to.shared.u64 t, %1; cvt.u32.u64 %0, t; }"
        : "=r"(a) : "l"(p));
    return a;
}

__device__ __forceinline__ uint32_t pack_bf2(__nv_bfloat16 a, __nv_bfloat16 b) {
    return (uint32_t)__bfloat16_as_ushort(a) |
           ((uint32_t)__bfloat16_as_ushort(b) << 16);
}

__device__ __forceinline__ void split_pack(float a, float b,
                                           uint32_t& h, uint32_t& l) {
    __nv_bfloat16 ha = __float2bfloat16_rn(a);
    __nv_bfloat16 hb = __float2bfloat16_rn(b);
    __nv_bfloat16 la = __float2bfloat16_rn(a - __bfloat162float(ha));
    __nv_bfloat16 lb = __float2bfloat16_rn(b - __bfloat162float(hb));
    h = pack_bf2(ha, hb);
    l = pack_bf2(la, lb);
}

__device__ __forceinline__ void ldsm_x4(uint32_t* r, uint32_t addr) {
    asm volatile("ldmatrix.sync.aligned.m8n8.x4.shared.b16 {%0,%1,%2,%3}, [%4];"
                 : "=r"(r[0]), "=r"(r[1]), "=r"(r[2]), "=r"(r[3]) : "r"(addr));
}

__device__ __forceinline__ void mma16816(float* d, const uint32_t* a,
                                         const uint32_t* b) {
    asm volatile("mma.sync.aligned.m16n8k16.row.col.f32.bf16.bf16.f32 "
                 "{%0,%1,%2,%3}, {%4,%5,%6,%7}, {%8,%9}, {%0,%1,%2,%3};"
                 : "+f"(d[0]), "+f"(d[1]), "+f"(d[2]), "+f"(d[3])
                 : "r"(a[0]), "r"(a[1]), "r"(a[2]), "r"(a[3]),
                   "r"(b[0]), "r"(b[1]));
}

__device__ __forceinline__ void cp16(uint32_t saddr, const void* gaddr) {
    asm volatile("cp.async.cg.shared.global [%0], [%1], 16;"
                 :: "r"(saddr), "l"(gaddr));
}

__device__ __forceinline__ void cp_commit() {
    asm volatile("cp.async.commit_group;" ::: "memory");
}
__device__ __forceinline__ void cp_wait1() {
    asm volatile("cp.async.wait_group 1;" ::: "memory");
}
__device__ __forceinline__ void cp_wait0() {
    asm volatile("cp.async.wait_group 0;" ::: "memory");
}

// ---------------------------------------------------------------------------
// Pre-pass: split fp32 sources into bf16 hi/lo.
// ---------------------------------------------------------------------------

__global__ void convert_split(const float* __restrict__ x,
                              const float* __restrict__ Wq,
                              const float* __restrict__ Wk,
                              const float* __restrict__ Wv,
                              const float* __restrict__ Wo)
{
    const float* src;
    __nv_bfloat16 *dh, *dl;
    int n;
    switch (blockIdx.y) {
        case 0: src = x;  dh = g_Xh;  dl = g_Xl;  n = TOKENS * DMODEL; break;
        case 1: src = Wq; dh = g_Wqh; dl = g_Wql; n = DMODEL * DMODEL; break;
        case 2: src = Wk; dh = g_Wkh; dl = g_Wkl; n = DMODEL * DMODEL; break;
        case 3: src = Wv; dh = g_Wvh; dl = g_Wvl; n = DMODEL * DMODEL; break;
        default: src = Wo; dh = g_Woh; dl = g_Wol; n = DMODEL * DMODEL; break;
    }
    int i = (blockIdx.x * blockDim.x + threadIdx.x) * 4;
    if (i >= n) return;
    float4 v = *(const float4*)(src + i);
    uint32_t h0, h1, l0, l1;
    split_pack(v.x, v.y, h0, l0);
    split_pack(v.z, v.w, h1, l1);
    *(uint2*)(dh + i) = make_uint2(h0, h1);
    *(uint2*)(dl + i) = make_uint2(l0, l1);
}

// ---------------------------------------------------------------------------
// Split-bf16 HMMA GEMM, cp.async 3-stage pipelined, CTA 128x256, BK=32.
// 8 warps 2x4, warp tile 64x64. Paired-x4 B-frag loads.
// ---------------------------------------------------------------------------

__device__ __forceinline__ uint32_t tile_off(int r, int c) {
    return (uint32_t)((r >> 1) * 128 + (((((r & 1) << 2) | c) ^ ((r >> 1) & 7)) << 4));
}

#define G_STAGE 49152
#define GEMM_SMEM_BYTES (3 * G_STAGE)

__global__ __launch_bounds__(256, 1) void gemm_bf16(float* __restrict__ Cout,
                                                    int qkv_mode)
{
    extern __shared__ char sm[];
    const uint32_t sb = smem_u32(sm);
    const int tid = threadIdx.x;
    const int lane = tid & 31;
    const int wid = tid >> 5;
    const int warp_m = wid >> 2;
    const int warp_n = wid & 3;
    const int z = blockIdx.z;

    const __nv_bfloat16 *Ah, *Al, *Bh, *Bl;
    if (qkv_mode) {
        Ah = g_Xh; Al = g_Xl;
        Bh = (z == 0) ? g_Wqh : (z == 1 ? g_Wkh : g_Wvh);
        Bl = (z == 0) ? g_Wql : (z == 1 ? g_Wkl : g_Wvl);
    } else {
        Ah = g_Oh; Al = g_Ol; Bh = g_Woh; Bl = g_Wol;
    }
    const int m0 = blockIdx.y * 128;
    const int n0 = blockIdx.x * 256;
    const __nv_bfloat16* Agh = Ah + (size_t)m0 * DMODEL;
    const __nv_bfloat16* Agl = Al + (size_t)m0 * DMODEL;
    const __nv_bfloat16* Bgh = Bh + (size_t)n0 * DMODEL;
    const __nv_bfloat16* Bgl = Bl + (size_t)n0 * DMODEL;

    const int cA = tid & 3;
    int rA[2]; uint32_t oA[2];
#pragma unroll
    for (int u = 0; u < 2; u++) { rA[u] = (u * 256 + tid) >> 2; oA[u] = tile_off(rA[u], cA); }
    int rB[4]; uint32_t oB[4];
#pragma unroll
    for (int u = 0; u < 4; u++) { rB[u] = (u * 256 + tid) >> 2; oB[u] = tile_off(rB[u], cA); }

    float acc[4][8][4];
#pragma unroll
    for (int i = 0; i < 4; i++)
#pragma unroll
        for (int j = 0; j < 8; j++)
#pragma unroll
            for (int u = 0; u < 4; u++) acc[i][j][u] = 0.f;

    const int a_mat = lane >> 3;
    const int a_khalf = a_mat >> 1;
    int rowA[4];
#pragma unroll
    for (int im = 0; im < 4; im++)
        rowA[im] = warp_m * 64 + im * 16 + (a_mat & 1) * 8 + (lane & 7);
    const int b_row4 = ((lane >> 4) << 3) + (lane & 7);
    const int b_chunk4 = (lane >> 3) & 1;

#define ISSUE(chv)                                                                 \
    do {                                                                           \
        const int _k0 = (chv) * 32;                                                \
        const uint32_t _bs = sb + (uint32_t)(((chv) % 3) * G_STAGE);               \
        cp16(_bs + oA[0],         Agh + (size_t)rA[0] * DMODEL + _k0 + cA * 8);    \
        cp16(_bs + oA[1],         Agh + (size_t)rA[1] * DMODEL + _k0 + cA * 8);    \
        cp16(_bs + 8192 + oA[0],  Agl + (size_t)rA[0] * DMODEL + _k0 + cA * 8);    \
        cp16(_bs + 8192 + oA[1],  Agl + (size_t)rA[1] * DMODEL + _k0 + cA * 8);    \
        cp16(_bs + 16384 + oB[0], Bgh + (size_t)rB[0] * DMODEL + _k0 + cA * 8);    \
        cp16(_bs + 16384 + oB[1], Bgh + (size_t)rB[1] * DMODEL + _k0 + cA * 8);    \
        cp16(_bs + 16384 + oB[2], Bgh + (size_t)rB[2] * DMODEL + _k0 + cA * 8);    \
        cp16(_bs + 16384 + oB[3], Bgh + (size_t)rB[3] * DMODEL + _k0 + cA * 8);    \
        cp16(_bs + 32768 + oB[0], Bgl + (size_t)rB[0] * DMODEL + _k0 + cA * 8);    \
        cp16(_bs + 32768 + oB[1], Bgl + (size_t)rB[1] * DMODEL + _k0 + cA * 8);    \
        cp16(_bs + 32768 + oB[2], Bgl + (size_t)rB[2] * DMODEL + _k0 + cA * 8);    \
        cp16(_bs + 32768 + oB[3], Bgl + (size_t)rB[3] * DMODEL + _k0 + cA * 8);    \
        cp_commit();                                                               \
    } while (0)

    ISSUE(0);
    ISSUE(1);

    for (int ch = 0; ch < 32; ch++) {
        if (ch + 1 < 32) cp_wait1(); else cp_wait0();
        __syncthreads();
        if (ch + 2 < 32) ISSUE(ch + 2);

        const uint32_t bs = sb + (uint32_t)((ch % 3) * G_STAGE);
        const uint32_t sAh = bs, sAl = bs + 8192;
        const uint32_t sBh = bs + 16384, sBl = bs + 32768;
#pragma unroll
        for (int kk = 0; kk < 2; kk++) {
            uint32_t ah[4][4], al[4][4];
#pragma unroll
            for (int im = 0; im < 4; im++) {
                uint32_t off = tile_off(rowA[im], kk * 2 + a_khalf);
                ldsm_x4(ah[im], sAh + off);
                ldsm_x4(al[im], sAl + off);
            }
#pragma unroll
            for (int inp = 0; inp < 4; inp++) {
                uint32_t bh4[4], bl4[4];
                uint32_t off = tile_off(warp_n * 64 + inp * 16 + b_row4,
                                        kk * 2 + b_chunk4);
                ldsm_x4(bh4, sBh + off);
                ldsm_x4(bl4, sBl + off);
#pragma unroll
                for (int im = 0; im < 4; im++) {
                    mma16816(acc[im][2 * inp], ah[im], bh4);
                    mma16816(acc[im][2 * inp], ah[im], bl4);
                    mma16816(acc[im][2 * inp], al[im], bh4);
                    mma16816(acc[im][2 * inp + 1], ah[im], bh4 + 2);
                    mma16816(acc[im][2 * inp + 1], ah[im], bl4 + 2);
                    mma16816(acc[im][2 * inp + 1], al[im], bh4 + 2);
                }
            }
        }
        __syncthreads();
    }
#undef ISSUE

    const int gid = lane >> 2;
    const int tig = lane & 3;
    if (qkv_mode) {
        if (z < 2) {
            __nv_bfloat16* Ch = (z == 0) ? g_Qh : g_Kh;
            __nv_bfloat16* Cl = (z == 0) ? g_Ql : g_Kl;
            const float scale = (z == 0) ? 0.125f : 1.0f;
#pragma unroll
            for (int im = 0; im < 4; im++) {
#pragma unroll
                for (int in = 0; in < 8; in++) {
                    int row = m0 + warp_m * 64 + im * 16 + gid;
                    int col = n0 + warp_n * 64 + in * 8 + tig * 2;
                    int h = col >> 6, hd = col & 63;
#pragma unroll
                    for (int half = 0; half < 2; half++) {
                        int rr = row + half * 8;
                        int bb = rr >> 11, s = rr & 2047;
                        size_t off = (((size_t)(bb * NHEADS + h) * SEQ + s) << 6) + hd;
                        uint32_t hh, ll;
                        split_pack(acc[im][in][half * 2] * scale,
                                   acc[im][in][half * 2 + 1] * scale, hh, ll);
                        *(uint32_t*)(Ch + off) = hh;
                        *(uint32_t*)(Cl + off) = ll;
                    }
                }
            }
        } else {
            // V: write TRANSPOSED [bh][d][s].
#pragma unroll
            for (int im = 0; im < 4; im++) {
#pragma unroll
                for (int in = 0; in < 8; in++) {
                    int row = m0 + warp_m * 64 + im * 16 + gid;
                    int col = n0 + warp_n * 64 + in * 8 + tig * 2;
                    int h = col >> 6, hd = col & 63;
#pragma unroll
                    for (int half = 0; half < 2; half++) {
                        int rr = row + half * 8;
                        int bb = rr >> 11, s = rr & 2047;
                        size_t base = ((size_t)(bb * NHEADS + h) * 64 + hd) * SEQ + s;
#pragma unroll
                        for (int e = 0; e < 2; e++) {
                            float v = acc[im][in][half * 2 + e];
                            __nv_bfloat16 hb = __float2bfloat16_rn(v);
                            __nv_bfloat16 lb =
                                __float2bfloat16_rn(v - __bfloat162float(hb));
                            g_Vh[base + (size_t)e * SEQ] = hb;
                            g_Vl[base + (size_t)e * SEQ] = lb;
                        }
                    }
                }
            }
        }
    } else {
#pragma unroll
        for (int im = 0; im < 4; im++) {
#pragma unroll
            for (int in = 0; in < 8; in++) {
                int row = m0 + warp_m * 64 + im * 16 + gid;
                int col = n0 + warp_n * 64 + in * 8 + tig * 2;
#pragma unroll
                for (int half = 0; half < 2; half++) {
                    int rr = row + half * 8;
                    float* dst = Cout + (size_t)rr * DMODEL + col;
                    dst[0] = acc[im][in][half * 2 + 0];
                    dst[1] = acc[im][in][half * 2 + 1];
                }
            }
        }
    }
}

// ---------------------------------------------------------------------------
// Flash attention (causal), split-bf16 HMMA. Br=128, Bc=64, 8 warps.
// K / Vt tiles 3-stage cp.async pipelined. Longest CTAs launch first.
// Smem: Q 32KB | 3 stages x 32KB = 128KB dynamic.
// ---------------------------------------------------------------------------

__device__ __forceinline__ uint32_t fl_off(int r, int c) {
    return (uint32_t)(r * 128 + ((c ^ (r & 7)) << 4));
}

#define F_SMEM_BYTES (32768 + 3 * 32768)

__global__ __launch_bounds__(256, 1) void flash_mma()
{
    extern __shared__ char sm[];
    const uint32_t sb = smem_u32(sm);
    const int tid = threadIdx.x;
    const int lane = tid & 31;
    const int wq = tid >> 5;
    const int qt = gridDim.x - 1 - blockIdx.x;   // longest first
    const int bh = blockIdx.y;
    const int q0 = qt * 128;
    const int T = 2 * qt + 2;

    const __nv_bfloat16* qbh = g_Qh + (size_t)(bh * SEQ + q0) * 64;
    const __nv_bfloat16* qbl = g_Ql + (size_t)(bh * SEQ + q0) * 64;
    const __nv_bfloat16* kbh = g_Kh + (size_t)bh * SEQ * 64;
    const __nv_bfloat16* kbl = g_Kl + (size_t)bh * SEQ * 64;
    const __nv_bfloat16* vth = g_Vh + (size_t)bh * 64 * SEQ;
    const __nv_bfloat16* vtl = g_Vl + (size_t)bh * 64 * SEQ;

    const uint32_t aQh = sb, aQl = sb + 16384;

#pragma unroll
    for (int u = 0; u < 4; u++) {
        int lin = u * 256 + tid;
        int r = lin >> 3, c = lin & 7;
        uint32_t off = fl_off(r, c);
        *(uint4*)(sm + off)         = *(const uint4*)(qbh + r * 64 + c * 8);
        *(uint4*)(sm + 16384 + off) = *(const uint4*)(qbl + r * 64 + c * 8);
    }

    int rF[2]; uint32_t oF[2];
#pragma unroll
    for (int u = 0; u < 2; u++) {
        int lin = u * 256 + tid;
        rF[u] = lin >> 3;
        oF[u] = fl_off(rF[u], lin & 7);
    }
    const int cF0 = (tid & 7) * 8, cF1 = ((256 + tid) & 7) * 8;

#define F_ISSUE(tt)                                                                 \
    do {                                                                            \
        const uint32_t _bs = sb + 32768u + (uint32_t)(((tt) % 3) * 32768);          \
        cp16(_bs + oF[0],         kbh + (size_t)((tt) * 64 + rF[0]) * 64 + cF0);    \
        cp16(_bs + oF[1],         kbh + (size_t)((tt) * 64 + rF[1]) * 64 + cF1);    \
        cp16(_bs + 8192 + oF[0],  kbl + (size_t)((tt) * 64 + rF[0]) * 64 + cF0);    \
        cp16(_bs + 8192 + oF[1],  kbl + (size_t)((tt) * 64 + rF[1]) * 64 + cF1);    \
        cp16(_bs + 16384 + oF[0], vth + (size_t)rF[0] * SEQ + (tt) * 64 + cF0);     \
        cp16(_bs + 16384 + oF[1], vth + (size_t)rF[1] * SEQ + (tt) * 64 + cF1);     \
        cp16(_bs + 24576 + oF[0], vtl + (size_t)rF[0] * SEQ + (tt) * 64 + cF0);     \
        cp16(_bs + 24576 + oF[1], vtl + (size_t)rF[1] * SEQ + (tt) * 64 + cF1);     \
        cp_commit();                                                                \
    } while (0)

    F_ISSUE(0);
    F_ISSUE(1);   // T >= 2 always

    const int a_mat = lane >> 3;
    const int a_khalf = a_mat >> 1;
    const int rowA = wq * 16 + (a_mat & 1) * 8 + (lane & 7);
    const int b_row4 = ((lane >> 4) << 3) + (lane & 7);
    const int b_chunk4 = (lane >> 3) & 1;
    const int gid = lane >> 2;
    const int tig = lane & 3;

    float m[2], l[2], o[8][4], s[8][4];
#pragma unroll
    for (int i = 0; i < 2; i++) { m[i] = neg_inf(); l[i] = 0.f; }
#pragma unroll
    for (int j = 0; j < 8; j++)
#pragma unroll
        for (int u = 0; u < 4; u++) o[j][u] = 0.f;

    for (int t = 0; t < T; t++) {
        if (t + 1 < T) cp_wait1(); else cp_wait0();
        __syncthreads();
        if (t + 2 < T) F_ISSUE(t + 2);

        const uint32_t bs = sb + 32768u + (uint32_t)((t % 3) * 32768);
        const uint32_t aKh = bs, aKl = bs + 8192;
        const uint32_t aVh = bs + 16384, aVl = bs + 24576;

        // ---- S = Q K^T ----
#pragma unroll
        for (int j = 0; j < 8; j++)
#pragma unroll
            for (int u = 0; u < 4; u++) s[j][u] = 0.f;

#pragma unroll
        for (int kk = 0; kk < 4; kk++) {
            uint32_t ah[4], al[4];
            uint32_t offa = fl_off(rowA, kk * 2 + a_khalf);
            ldsm_x4(ah, aQh + offa);
            ldsm_x4(al, aQl + offa);
#pragma unroll
            for (int jp = 0; jp < 4; jp++) {
                uint32_t bh4[4], bl4[4];
                uint32_t offb = fl_off(jp * 16 + b_row4, kk * 2 + b_chunk4);
                ldsm_x4(bh4, aKh + offb);
                ldsm_x4(bl4, aKl + offb);
                mma16816(s[2 * jp], ah, bh4);
                mma16816(s[2 * jp], ah, bl4);
                mma16816(s[2 * jp], al, bh4);
                mma16816(s[2 * jp + 1], ah, bh4 + 2);
                mma16816(s[2 * jp + 1], ah, bl4 + 2);
                mma16816(s[2 * jp + 1], al, bh4 + 2);
            }
        }

        if (t >= 2 * qt) {
#pragma unroll
            for (int j = 0; j < 8; j++) {
#pragma unroll
                for (int u = 0; u < 4; u++) {
                    int row = q0 + wq * 16 + (u >> 1) * 8 + gid;
                    int col = t * 64 + j * 8 + tig * 2 + (u & 1);
                    if (col > row) s[j][u] = neg_inf();
                }
            }
        }

        // ---- Online softmax ----
#pragma unroll
        for (int i = 0; i < 2; i++) {
            float mx = neg_inf();
#pragma unroll
            for (int j = 0; j < 8; j++) {
                mx = fmaxf(mx, s[j][i * 2]);
                mx = fmaxf(mx, s[j][i * 2 + 1]);
            }
            mx = fmaxf(mx, __shfl_xor_sync(0xffffffffu, mx, 1));
            mx = fmaxf(mx, __shfl_xor_sync(0xffffffffu, mx, 2));
            float mnew = fmaxf(m[i], mx);
            float corr = __expf(m[i] - mnew);
            float rs = 0.f;
#pragma unroll
            for (int j = 0; j < 8; j++) {
                float e0 = __expf(s[j][i * 2] - mnew);
                float e1 = __expf(s[j][i * 2 + 1] - mnew);
                s[j][i * 2] = e0;
                s[j][i * 2 + 1] = e1;
                rs += e0 + e1;
            }
            rs += __shfl_xor_sync(0xffffffffu, rs, 1);
            rs += __shfl_xor_sync(0xffffffffu, rs, 2);
            l[i] = l[i] * corr + rs;
            m[i] = mnew;
#pragma unroll
            for (int j = 0; j < 8; j++) {
                o[j][i * 2] *= corr;
                o[j][i * 2 + 1] *= corr;
            }
        }

        // ---- O += P Vt ----
#pragma unroll
        for (int kk = 0; kk < 4; kk++) {
            uint32_t ph[4], pl[4];
#pragma unroll
            for (int half = 0; half < 2; half++) {
                const float* sv = s[2 * kk + half];
                split_pack(sv[0], sv[1], ph[half * 2], pl[half * 2]);
                split_pack(sv[2], sv[3], ph[half * 2 + 1], pl[half * 2 + 1]);
            }
#pragma unroll
            for (int jp = 0; jp < 4; jp++) {
                uint32_t vh4[4], vl4[4];
                uint32_t offv = fl_off(jp * 16 + b_row4, kk * 2 + b_chunk4);
                ldsm_x4(vh4, aVh + offv);
                ldsm_x4(vl4, aVl + offv);
                mma16816(o[2 * jp], ph, vh4);
                mma16816(o[2 * jp], ph, vl4);
                mma16816(o[2 * jp], pl, vh4);
                mma16816(o[2 * jp + 1], ph, vh4 + 2);
                mma16816(o[2 * jp + 1], ph, vl4 + 2);
                mma16816(o[2 * jp + 1], pl, vh4 + 2);
            }
        }
    }
#undef F_ISSUE

    const int bb = bh >> 4;
    const int h = bh & 15;
    float inv0 = 1.f / l[0];
    float inv1 = 1.f / l[1];
#pragma unroll
    for (int j = 0; j < 8; j++) {
        int col = h * 64 + j * 8 + tig * 2;
        int r0 = q0 + wq * 16 + gid;
        size_t off0 = (size_t)(bb * SEQ + r0) * DMODEL + col;
        size_t off1 = (size_t)(bb * SEQ + r0 + 8) * DMODEL + col;
        uint32_t hh, ll;
        split_pack(o[j][0] * inv0, o[j][1] * inv0, hh, ll);
        *(uint32_t*)(g_Oh + off0) = hh;
        *(uint32_t*)(g_Ol + off0) = ll;
        split_pack(o[j][2] * inv1, o[j][3] * inv1, hh, ll);
        *(uint32_t*)(g_Oh + off1) = hh;
        *(uint32_t*)(g_Ol + off1) = ll;
    }
}

// ---------------------------------------------------------------------------

extern "C" void kernel_launch(void* const* d_in, const int* in_sizes, int n_in,
                              void* d_out, int out_size)
{
    (void)in_sizes; (void)n_in; (void)out_size;
    const float* x  = (const float*)d_in[0];
    const float* Wq = (const float*)d_in[1];
    const float* Wk = (const float*)d_in[2];
    const float* Wv = (const float*)d_in[3];
    const float* Wo = (const float*)d_in[4];
    float* out = (float*)d_out;

    cudaFuncSetAttribute(gemm_bf16, cudaFuncAttributeMaxDynamicSharedMemorySize,
                         GEMM_SMEM_BYTES);
    cudaFuncSetAttribute(flash_mma, cudaFuncAttributeMaxDynamicSharedMemorySize,
                         F_SMEM_BYTES);

    convert_split<<<dim3(4096, 5), 256>>>(x, Wq, Wk, Wv, Wo);

    dim3 gqkv(DMODEL / 256, TOKENS / 128, 3);   // (4, 32, 3)
    gemm_bf16<<<gqkv, 256, GEMM_SMEM_BYTES>>>(nullptr, 1);

    dim3 gatt(SEQ / 128, 2 * NHEADS);           // (16, 32)
    flash_mma<<<gatt, 256, F_SMEM_BYTES>>>();

    dim3 gout(DMODEL / 256, TOKENS / 128, 1);   // (4, 32)
    gemm_bf16<<<gout, 256, GEMM_SMEM_BYTES>>>(out, 0);
}